// round 10
// baseline (speedup 1.0000x reference)
#include <cuda_runtime.h>
#include <cuda_bf16.h>
#include <math.h>
#include <stdint.h>

#define BB 64
#define SS 1024
#define DD 256
#define NLAYERS 8
#define KANH 32
#define NCLS 1000
#define EPSF 1e-8f
#define PI_F 3.14159265358979323846f
#define NCHUNK 16
#define BD (BB*DD)
#define WSTRIDE 260

// ---------------- persistent device scratch ----------------
__device__ float g_xc[BB*SS*DD];
__device__ float g_yc[BB*SS*DD];
__device__ float g_xp[NCHUNK*BD];
__device__ float g_yp[NCHUNK*BD];
__device__ float g_dx[BD];
__device__ float g_dy[BD];
__device__ __nv_bfloat16 g_ah[BB*SS*DD];     // A hi
__device__ __nv_bfloat16 g_al[BB*SS*DD];     // A lo
__device__ __nv_bfloat16 g_bhT[512*256];     // W hi, transposed [n][k]
__device__ __nv_bfloat16 g_blT[512*256];     // W lo, transposed [n][k]

__device__ __forceinline__ float gelu_exact(float v) {
    return 0.5f * v * (1.0f + erff(v * 0.70710678118654752440f));
}

// ---------------- split-bf16 conversion kernels ----------------
__global__ __launch_bounds__(256) void k_cvt_a(const float* __restrict__ x) {
    const size_t i = ((size_t)blockIdx.x * 256 + threadIdx.x) * 4;
    float4 v = *(const float4*)(x + i);
    __nv_bfloat16 h0 = __float2bfloat16(v.x);
    __nv_bfloat16 h1 = __float2bfloat16(v.y);
    __nv_bfloat16 h2 = __float2bfloat16(v.z);
    __nv_bfloat16 h3 = __float2bfloat16(v.w);
    g_ah[i+0] = h0; g_ah[i+1] = h1; g_ah[i+2] = h2; g_ah[i+3] = h3;
    g_al[i+0] = __float2bfloat16(v.x - __bfloat162float(h0));
    g_al[i+1] = __float2bfloat16(v.y - __bfloat162float(h1));
    g_al[i+2] = __float2bfloat16(v.z - __bfloat162float(h2));
    g_al[i+3] = __float2bfloat16(v.w - __bfloat162float(h3));
}

__global__ __launch_bounds__(256) void k_cvt_w(const float* __restrict__ W) {
    const int idx = blockIdx.x * 256 + threadIdx.x;   // output [n][k], 512*256
    const int n = idx >> 8, k = idx & 255;
    const float v = W[k * 512 + n];
    __nv_bfloat16 h = __float2bfloat16(v);
    g_bhT[idx] = h;
    g_blT[idx] = __float2bfloat16(v - __bfloat162float(h));
}

// ---------------- tensor-core embed GEMM + fused polar epilogue ----------------
// One block = 128 rows, full K (256) of A hi+lo in smem, sweep N in 4 paired
// (h1 cols [64j,64j+64), h2 cols [256+64j, ...)) iterations.
// 8 warps: wm = w&3 -> 32-row slice, half = w>>2 -> h1 (0) or h2 (1) columns.

#define SA_STRIDE 264                       // bf16 per A smem row (pad 8)
#define SA_BYTES  (128*SA_STRIDE*2)         // 67584
#define SB_STRIDE 72                        // bf16 per B smem row (pad 8)
#define SB_ARR    (64*SB_STRIDE*2)          // 9216 bytes per array
#define SB_OFF    (2*SA_BYTES)              // 135168
#define STAGE_OFF (SB_OFF + 4*SB_ARR)       // 172032
#define STAGE_STRIDE 65
#define SUMX_OFF  (STAGE_OFF + 128*STAGE_STRIDE*4)   // 205312
#define SUMY_OFF  (SUMX_OFF + 4*64*4)                // 206336
#define SBIAS_OFF (SUMY_OFF + 4*64*4)                // 207360
#define SMEM_TOTAL (SBIAS_OFF + 512*4)               // 209408

__device__ __forceinline__ void mma16816(float c[4], const uint32_t a[4], const uint32_t b[2]) {
    asm volatile("mma.sync.aligned.m16n8k16.row.col.f32.bf16.bf16.f32 "
                 "{%0,%1,%2,%3}, {%4,%5,%6,%7}, {%8,%9}, {%0,%1,%2,%3};"
                 : "+f"(c[0]), "+f"(c[1]), "+f"(c[2]), "+f"(c[3])
                 : "r"(a[0]), "r"(a[1]), "r"(a[2]), "r"(a[3]), "r"(b[0]), "r"(b[1]));
}

__global__ __launch_bounds__(256) void k_gemm(const float* __restrict__ bias) {
    extern __shared__ char smem[];
    __nv_bfloat16* sAh = (__nv_bfloat16*)smem;
    __nv_bfloat16* sAl = (__nv_bfloat16*)(smem + SA_BYTES);
    float* stage = (float*)(smem + STAGE_OFF);
    float* sumx  = (float*)(smem + SUMX_OFF);
    float* sumy  = (float*)(smem + SUMY_OFF);
    float* sbias = (float*)(smem + SBIAS_OFF);

    const int t = threadIdx.x;
    const int lane = t & 31, w = t >> 5;
    const int g = lane >> 2, tg = lane & 3;
    const int wm = w & 3, half = w >> 2;
    const int bm = blockIdx.x * 128;
    const int bidx = bm >> 10;                  // batch
    const int chunkbase = (bm & 1023) >> 6;     // 64-row chunk base within S

    // bias to smem
    sbias[t] = bias[t];
    sbias[256 + t] = bias[256 + t];

    // A hi/lo tiles: 128 x 256 bf16 each, padded rows
#pragma unroll
    for (int it = 0; it < 16; it++) {
        const int idx = (it * 256 + t) * 8;
        const int row = idx >> 8, col = idx & 255;
        *(uint4*)(sAh + row * SA_STRIDE + col) = *(const uint4*)(g_ah + (size_t)bm * 256 + idx);
        *(uint4*)(sAl + row * SA_STRIDE + col) = *(const uint4*)(g_al + (size_t)bm * 256 + idx);
    }

    for (int j = 0; j < 4; j++) {
        float acc[2][8][4];
#pragma unroll
        for (int mt = 0; mt < 2; mt++)
#pragma unroll
            for (int nt = 0; nt < 8; nt++)
#pragma unroll
                for (int c = 0; c < 4; c++) acc[mt][nt][c] = 0.0f;

        for (int kc = 0; kc < 4; kc++) {
            __syncthreads();
            // load B tiles: arr 0=bh(h1) 1=bh(h2) 2=bl(h1) 3=bl(h2); 64 n-rows x 64 k
            {
                const int arr = t >> 6, n = t & 63;
                const __nv_bfloat16* src = (arr < 2) ? g_bhT : g_blT;
                const int nglob = (arr & 1) * 256 + j * 64 + n;
                const uint4* s4 = (const uint4*)(src + nglob * 256 + kc * 64);
                uint4* d4 = (uint4*)(smem + SB_OFF + arr * SB_ARR + n * SB_STRIDE * 2);
#pragma unroll
                for (int q = 0; q < 8; q++) d4[q] = s4[q];
            }
            __syncthreads();

            const __nv_bfloat16* sBh = (const __nv_bfloat16*)(smem + SB_OFF + half * SB_ARR);
            const __nv_bfloat16* sBl = (const __nv_bfloat16*)(smem + SB_OFF + (2 + half) * SB_ARR);

#pragma unroll
            for (int kk = 0; kk < 4; kk++) {
                const int kb = kc * 64 + kk * 16;
                uint32_t ah[2][4], bh[8][2];
#pragma unroll
                for (int mt = 0; mt < 2; mt++) {
                    const __nv_bfloat16* p = sAh + (wm * 32 + mt * 16 + g) * SA_STRIDE + kb + tg * 2;
                    ah[mt][0] = *(const uint32_t*)(p);
                    ah[mt][1] = *(const uint32_t*)(p + 8 * SA_STRIDE);
                    ah[mt][2] = *(const uint32_t*)(p + 8);
                    ah[mt][3] = *(const uint32_t*)(p + 8 * SA_STRIDE + 8);
                }
#pragma unroll
                for (int nt = 0; nt < 8; nt++) {
                    const __nv_bfloat16* p = sBh + (nt * 8 + g) * SB_STRIDE + kk * 16 + tg * 2;
                    bh[nt][0] = *(const uint32_t*)(p);
                    bh[nt][1] = *(const uint32_t*)(p + 8);
                }
#pragma unroll
                for (int mt = 0; mt < 2; mt++)
#pragma unroll
                    for (int nt = 0; nt < 8; nt++) mma16816(acc[mt][nt], ah[mt], bh[nt]);

                // a_lo * b_hi
                {
                    uint32_t al[2][4];
#pragma unroll
                    for (int mt = 0; mt < 2; mt++) {
                        const __nv_bfloat16* p = sAl + (wm * 32 + mt * 16 + g) * SA_STRIDE + kb + tg * 2;
                        al[mt][0] = *(const uint32_t*)(p);
                        al[mt][1] = *(const uint32_t*)(p + 8 * SA_STRIDE);
                        al[mt][2] = *(const uint32_t*)(p + 8);
                        al[mt][3] = *(const uint32_t*)(p + 8 * SA_STRIDE + 8);
                    }
#pragma unroll
                    for (int mt = 0; mt < 2; mt++)
#pragma unroll
                        for (int nt = 0; nt < 8; nt++) mma16816(acc[mt][nt], al[mt], bh[nt]);
                }
                // a_hi * b_lo
                {
                    uint32_t bl[8][2];
#pragma unroll
                    for (int nt = 0; nt < 8; nt++) {
                        const __nv_bfloat16* p = sBl + (nt * 8 + g) * SB_STRIDE + kk * 16 + tg * 2;
                        bl[nt][0] = *(const uint32_t*)(p);
                        bl[nt][1] = *(const uint32_t*)(p + 8);
                    }
#pragma unroll
                    for (int mt = 0; mt < 2; mt++)
#pragma unroll
                        for (int nt = 0; nt < 8; nt++) mma16816(acc[mt][nt], ah[mt], bl[nt]);
                }
            }
        }

        // -------- epilogue for this N pair-chunk --------
        if (half == 1) {   // stage h2 (+bias)
#pragma unroll
            for (int mt = 0; mt < 2; mt++)
#pragma unroll
                for (int nt = 0; nt < 8; nt++) {
                    const int r0 = wm * 32 + mt * 16 + g;
                    const int col = nt * 8 + tg * 2;
                    const int d = j * 64 + col;
                    stage[r0 * STAGE_STRIDE + col]           = acc[mt][nt][0] + sbias[256 + d];
                    stage[r0 * STAGE_STRIDE + col + 1]       = acc[mt][nt][1] + sbias[256 + d + 1];
                    stage[(r0 + 8) * STAGE_STRIDE + col]     = acc[mt][nt][2] + sbias[256 + d];
                    stage[(r0 + 8) * STAGE_STRIDE + col + 1] = acc[mt][nt][3] + sbias[256 + d + 1];
                }
        }
        __syncthreads();
        if (half == 0) {   // combine h1 + staged h2 -> polar -> write + column sums
            float csx[16], csy[16];
#pragma unroll
            for (int q = 0; q < 16; q++) { csx[q] = 0.0f; csy[q] = 0.0f; }
#pragma unroll
            for (int mt = 0; mt < 2; mt++)
#pragma unroll
                for (int nt = 0; nt < 8; nt++) {
                    const int col = nt * 8 + tg * 2;
                    const int d = j * 64 + col;
                    const float b0 = sbias[d], b1v = sbias[d + 1];
#pragma unroll
                    for (int rh = 0; rh < 2; rh++) {
                        const int row = wm * 32 + mt * 16 + g + rh * 8;
                        const float h1a = acc[mt][nt][rh * 2 + 0] + b0;
                        const float h1b = acc[mt][nt][rh * 2 + 1] + b1v;
                        const float h2a = stage[row * STAGE_STRIDE + col];
                        const float h2b = stage[row * STAGE_STRIDE + col + 1];
                        const float ra = fabsf(h1a) + 0.1f;
                        const float rb = fabsf(h1b) + 0.1f;
                        float sa, ca, sb, cb;
                        sincosf(PI_F * h2a, &sa, &ca);
                        sincosf(PI_F * h2b, &sb, &cb);
                        const float xa = ra * ca, ya = ra * sa;
                        const float xb = rb * cb, yb = rb * sb;
                        float2 xv; xv.x = xa; xv.y = xb;
                        float2 yv; yv.x = ya; yv.y = yb;
                        *(float2*)(g_xc + (size_t)(bm + row) * 256 + d) = xv;
                        *(float2*)(g_yc + (size_t)(bm + row) * 256 + d) = yv;
                        csx[nt * 2]     += xa;  csx[nt * 2 + 1] += xb;
                        csy[nt * 2]     += ya;  csy[nt * 2 + 1] += yb;
                    }
                }
            // reduce over g (lanes xor 4,8,16): each col-sum covers the warp's 32 rows
#pragma unroll
            for (int off = 4; off <= 16; off <<= 1)
#pragma unroll
                for (int q = 0; q < 16; q++) {
                    csx[q] += __shfl_xor_sync(0xffffffffu, csx[q], off);
                    csy[q] += __shfl_xor_sync(0xffffffffu, csy[q], off);
                }
            if (lane < 4) {
#pragma unroll
                for (int nt = 0; nt < 8; nt++) {
#pragma unroll
                    for (int e = 0; e < 2; e++) {
                        const int col = nt * 8 + tg * 2 + e;
                        sumx[wm * 64 + col] = csx[nt * 2 + e];
                        sumy[wm * 64 + col] = csy[nt * 2 + e];
                    }
                }
            }
        }
        __syncthreads();
        if (t < 128) {     // chunk (64-row) sums: warp pairs (0,1) and (2,3)
            const int chunk = t >> 6, col = t & 63;
            const float xs = sumx[(chunk * 2) * 64 + col] + sumx[(chunk * 2 + 1) * 64 + col];
            const float ys = sumy[(chunk * 2) * 64 + col] + sumy[(chunk * 2 + 1) * 64 + col];
            const int cg = chunkbase + chunk;
            const int d = j * 64 + col;
            g_xp[cg * BD + bidx * DD + d] = xs;
            g_yp[cg * BD + bidx * DD + d] = ys;
        }
    }
}

// ---------------- all 8 KAN layers in one kernel ----------------
__global__ __launch_bounds__(256) void k_mlp_all(const float* __restrict__ mw1, const float* __restrict__ mb1,
                                                 const float* __restrict__ mw2, const float* __restrict__ mb2,
                                                 const float* __restrict__ pw1, const float* __restrict__ pb1,
                                                 const float* __restrict__ pw2, const float* __restrict__ pb2) {
    __shared__ float w[NLAYERS * WSTRIDE];
    const int t = threadIdx.x;
    for (int idx = t; idx < NLAYERS * WSTRIDE; idx += 256) {
        const int l = idx / WSTRIDE;
        const int o = idx - l * WSTRIDE;
        float v = 0.0f;
        if      (o < 32)  v = mw1[l * 32 + o];
        else if (o < 64)  v = mb1[l * 32 + (o - 32)];
        else if (o < 96)  v = mw2[l * 32 + (o - 64)];
        else if (o < 160) v = pw1[l * 64 + (o - 96)];
        else if (o < 192) v = pb1[l * 32 + (o - 160)];
        else if (o < 256) v = pw2[l * 64 + (o - 192)];
        else if (o == 256) v = mb2[l];
        else if (o == 257) v = pb2[2 * l];
        else if (o == 258) v = pb2[2 * l + 1];
        w[idx] = v;
    }
    __syncthreads();

    const int k = blockIdx.x * 256 + t;
    float xs = 0.0f, ys = 0.0f;
#pragma unroll
    for (int c = 0; c < NCHUNK; c++) { xs += g_xp[c * BD + k]; ys += g_yp[c * BD + k]; }
    float xm = xs * (1.0f / SS), ym = ys * (1.0f / SS);
    float DX = 0.0f, DY = 0.0f;

    for (int l = 0; l < NLAYERS; l++) {
        const float* wl = w + l * WSTRIDE;
        const float ragg  = sqrtf(xm * xm + ym * ym + EPSF);
        const float thagg = atan2f(ym, xm);
        const float logr = logf(ragg + EPSF);
        float acc = 0.0f;
#pragma unroll
        for (int jj = 0; jj < 32; jj++) {
            const float u = fmaf(logr, wl[jj], wl[32 + jj]);
            acc = fmaf(gelu_exact(u), wl[64 + jj], acc);
        }
        const float rt = expf(acc + wl[256]);
        float s0, c0;
        sincosf(thagg, &s0, &c0);
        float p0 = 0.0f, p1 = 0.0f;
#pragma unroll
        for (int jj = 0; jj < 32; jj++) {
            const float u = fmaf(s0, wl[96 + jj], fmaf(c0, wl[128 + jj], wl[160 + jj]));
            const float gg = gelu_exact(u);
            p0 = fmaf(gg, wl[192 + 2 * jj],     p0);
            p1 = fmaf(gg, wl[192 + 2 * jj + 1], p1);
        }
        p0 += wl[257]; p1 += wl[258];
        const float nrm = sqrtf(p0 * p0 + p1 * p1 + EPSF);
        const float tht = atan2f(p0 / nrm, p1 / nrm);
        float sd, cd;
        sincosf(tht, &sd, &cd);
        const float dx = rt * cd, dy = rt * sd;
        xm += dx; ym += dy;
        DX += dx; DY += dy;
    }
    g_dx[k] = DX;
    g_dy[k] = DY;
}

// ---------------- final pass: r = sqrt((xc0+DX)^2 + (yc0+DY)^2 + eps), chunk sums ----------------
__global__ __launch_bounds__(256) void k_final() {
    __shared__ float sh[4][64][4];
    const int b = blockIdx.y, chunk = blockIdx.x, t = threadIdx.x;
    const int c4 = t & 63, rsub = t >> 6;
    const int dbase = c4 * 4;

    const float4 dxv = *(const float4*)(g_dx + b * DD + dbase);
    const float4 dyv = *(const float4*)(g_dy + b * DD + dbase);

    float s[4] = {0.f, 0.f, 0.f, 0.f};
    const size_t rowbase = (size_t)b * SS + (size_t)chunk * 64;
#pragma unroll 4
    for (int i = 0; i < 16; i++) {
        const size_t idx = (rowbase + rsub + 4 * i) * DD + dbase;
        const float4 xv = *(const float4*)(g_xc + idx);
        const float4 yv = *(const float4*)(g_yc + idx);
        float x0 = xv.x + dxv.x, y0 = yv.x + dyv.x;
        float x1 = xv.y + dxv.y, y1 = yv.y + dyv.y;
        float x2 = xv.z + dxv.z, y2 = yv.z + dyv.z;
        float x3 = xv.w + dxv.w, y3 = yv.w + dyv.w;
        s[0] += sqrtf(fmaf(x0, x0, fmaf(y0, y0, EPSF)));
        s[1] += sqrtf(fmaf(x1, x1, fmaf(y1, y1, EPSF)));
        s[2] += sqrtf(fmaf(x2, x2, fmaf(y2, y2, EPSF)));
        s[3] += sqrtf(fmaf(x3, x3, fmaf(y3, y3, EPSF)));
    }
#pragma unroll
    for (int jj = 0; jj < 4; jj++) sh[rsub][c4][jj] = s[jj];
    __syncthreads();
    if (rsub == 0) {
#pragma unroll
        for (int jj = 0; jj < 4; jj++) {
            float tot = sh[0][c4][jj] + sh[1][c4][jj] + sh[2][c4][jj] + sh[3][c4][jj];
            g_xp[chunk * BD + b * DD + dbase + jj] = tot;
        }
    }
}

// ---------------- classifier ----------------
__global__ __launch_bounds__(256) void k_cls(const float* __restrict__ w1, const float* __restrict__ b1,
                                             const float* __restrict__ w2, const float* __restrict__ b2,
                                             float* __restrict__ out) {
    __shared__ float p[DD];
    __shared__ float hp[8][33];
    __shared__ float h[KANH];
    const int b = blockIdx.x, t = threadIdx.x;
    float s = 0.0f;
#pragma unroll
    for (int c = 0; c < NCHUNK; c++) s += g_xp[c * BD + b * DD + t];
    p[t] = s * (1.0f / SS);
    __syncthreads();
    {
        const int jj = t & 31, sl = t >> 5;
        float a = 0.0f;
#pragma unroll
        for (int q = 0; q < 32; q++) {
            const int d2 = sl * 32 + q;
            a = fmaf(p[d2], w1[d2 * KANH + jj], a);
        }
        hp[sl][jj] = a;
    }
    __syncthreads();
    if (t < KANH) {
        float a = b1[t];
#pragma unroll
        for (int s8 = 0; s8 < 8; s8++) a += hp[s8][t];
        h[t] = gelu_exact(a);
    }
    __syncthreads();
    for (int c = t; c < NCLS; c += 256) {
        float a = b2[c];
#pragma unroll
        for (int jj = 0; jj < KANH; jj++) a = fmaf(h[jj], w2[jj * NCLS + c], a);
        out[b * NCLS + c] = a;
    }
}

// ---------------- launch ----------------
extern "C" void kernel_launch(void* const* d_in, const int* in_sizes, int n_in,
                              void* d_out, int out_size) {
    const float* x   = (const float*)d_in[0];
    const float* ew  = (const float*)d_in[1];
    const float* eb  = (const float*)d_in[2];
    const float* mw1 = (const float*)d_in[3];
    const float* mb1 = (const float*)d_in[4];
    const float* mw2 = (const float*)d_in[5];
    const float* mb2 = (const float*)d_in[6];
    const float* pw1 = (const float*)d_in[7];
    const float* pb1 = (const float*)d_in[8];
    const float* pw2 = (const float*)d_in[9];
    const float* pb2 = (const float*)d_in[10];
    const float* cw1 = (const float*)d_in[11];
    const float* cb1 = (const float*)d_in[12];
    const float* cw2 = (const float*)d_in[13];
    const float* cb2 = (const float*)d_in[14];
    float* out = (float*)d_out;

    cudaFuncSetAttribute(k_gemm, cudaFuncAttributeMaxDynamicSharedMemorySize, SMEM_TOTAL);

    k_cvt_a<<<(BB * SS * DD) / (256 * 4), 256>>>(x);
    k_cvt_w<<<512, 256>>>(ew);

    k_gemm<<<(BB * SS) / 128, 256, SMEM_TOTAL>>>(eb);

    k_mlp_all<<<BD / 256, 256>>>(mw1, mb1, mw2, mb2, pw1, pb1, pw2, pb2);

    dim3 fgrid(NCHUNK, BB);
    k_final<<<fgrid, 256>>>();

    k_cls<<<BB, 256>>>(cw1, cb1, cw2, cb2, out);
}

// round 11
// speedup vs baseline: 1.2851x; 1.2851x over previous
#include <cuda_runtime.h>
#include <math.h>

#define BB 64
#define SS 1024
#define DD 256
#define NLAYERS 8
#define KANH 32
#define NCLS 1000
#define EPSF 1e-8f
#define PI_F 3.14159265358979323846f
#define NCHUNK 16          /* S split into 16 chunks of 64 rows for deterministic partial sums */
#define BD (BB*DD)         /* 16384 */
#define WSTRIDE 260        /* per-layer weight block in shared */

// ---------------- persistent device scratch (no allocations allowed) ----------------
__device__ float g_xc[BB*SS*DD];      // xc0 (initial Cartesian state)
__device__ float g_yc[BB*SS*DD];      // yc0
__device__ float g_xp[NCHUNK*BD];     // per-chunk partial sums (xc0 sums, then final r sums)
__device__ float g_yp[NCHUNK*BD];     // per-chunk partial sums of yc0
__device__ float g_dx[BD];            // total accumulated DX over 8 layers
__device__ float g_dy[BD];            // total accumulated DY

__device__ __forceinline__ float gelu_exact(float v) {
    return 0.5f * v * (1.0f + erff(v * 0.70710678118654752440f));
}

// ---------------- 1) embed GEMM fused with polar init + chunk reduction ----------------
// Each block: 128 rows x 64 d-columns, computing BOTH h1 (W cols d) and h2 (W cols d+256).
// Double-buffered smem mainloop: one __syncthreads per K tile, next tile prefetched
// into registers while computing the current one.
__global__ __launch_bounds__(256) void k_embed_fused(const float* __restrict__ A,
                                                     const float* __restrict__ W,
                                                     const float* __restrict__ bias) {
    __shared__ float As[2][16][128];   // transposed: As[buf][k][m]  (reused as reduction scratch)
    __shared__ float Bs1[2][16][64];
    __shared__ float Bs2[2][16][64];

    const int tid  = threadIdx.x;
    const int bm   = blockIdx.y * 128;
    const int bn   = blockIdx.x * 64;
    const int tx   = tid & 15;          // 16 thread-cols * 4
    const int ty   = tid >> 4;          // 16 thread-rows * 8
    const int arow = tid >> 2;          // 0..63 (and +64)
    const int acol = (tid & 3) << 2;    // 0,4,8,12
    const int bkr  = tid >> 4;          // 0..15
    const int bc   = (tid & 15) << 2;   // 0..60

    const float* Arow0 = A + (size_t)(bm + arow)      * 256 + acol;
    const float* Arow1 = A + (size_t)(bm + arow + 64) * 256 + acol;
    const float* Wr1   = W + (size_t)bkr * 512 + bn + bc;
    const float* Wr2   = W + (size_t)bkr * 512 + bn + 256 + bc;

    float acc1[8][4], acc2[8][4];
#pragma unroll
    for (int j = 0; j < 8; j++)
#pragma unroll
        for (int l = 0; l < 4; l++) { acc1[j][l] = 0.0f; acc2[j][l] = 0.0f; }

    // ---- preload tile 0 into buffer 0 ----
    {
        float4 a0 = *(const float4*)(Arow0);
        float4 a1 = *(const float4*)(Arow1);
        As[0][acol + 0][arow]      = a0.x; As[0][acol + 1][arow]      = a0.y;
        As[0][acol + 2][arow]      = a0.z; As[0][acol + 3][arow]      = a0.w;
        As[0][acol + 0][arow + 64] = a1.x; As[0][acol + 1][arow + 64] = a1.y;
        As[0][acol + 2][arow + 64] = a1.z; As[0][acol + 3][arow + 64] = a1.w;
        *(float4*)&Bs1[0][bkr][bc] = *(const float4*)(Wr1);
        *(float4*)&Bs2[0][bkr][bc] = *(const float4*)(Wr2);
    }
    __syncthreads();

    for (int t0 = 0; t0 < 16; t0++) {
        const int cur = t0 & 1;
        float4 pa0, pa1, pb1, pb2;
        if (t0 < 15) {
            const int k0 = (t0 + 1) * 16;
            pa0 = *(const float4*)(Arow0 + k0);
            pa1 = *(const float4*)(Arow1 + k0);
            pb1 = *(const float4*)(Wr1 + (size_t)k0 * 512);
            pb2 = *(const float4*)(Wr2 + (size_t)k0 * 512);
        }

#pragma unroll
        for (int k = 0; k < 16; k++) {
            float a[8], b1[4], b2[4];
            *(float4*)(a)      = *(const float4*)&As[cur][k][ty * 8];
            *(float4*)(a + 4)  = *(const float4*)&As[cur][k][ty * 8 + 4];
            *(float4*)(b1)     = *(const float4*)&Bs1[cur][k][tx * 4];
            *(float4*)(b2)     = *(const float4*)&Bs2[cur][k][tx * 4];
#pragma unroll
            for (int j = 0; j < 8; j++)
#pragma unroll
                for (int l = 0; l < 4; l++) {
                    acc1[j][l] = fmaf(a[j], b1[l], acc1[j][l]);
                    acc2[j][l] = fmaf(a[j], b2[l], acc2[j][l]);
                }
        }

        if (t0 < 15) {
            const int nxt = cur ^ 1;
            As[nxt][acol + 0][arow]      = pa0.x; As[nxt][acol + 1][arow]      = pa0.y;
            As[nxt][acol + 2][arow]      = pa0.z; As[nxt][acol + 3][arow]      = pa0.w;
            As[nxt][acol + 0][arow + 64] = pa1.x; As[nxt][acol + 1][arow + 64] = pa1.y;
            As[nxt][acol + 2][arow + 64] = pa1.z; As[nxt][acol + 3][arow + 64] = pa1.w;
            *(float4*)&Bs1[nxt][bkr][bc] = pb1;
            *(float4*)&Bs2[nxt][bkr][bc] = pb2;
        }
        __syncthreads();
    }

    float4 bv1 = *(const float4*)(bias + bn + tx * 4);
    float4 bv2 = *(const float4*)(bias + 256 + bn + tx * 4);
    float bb1[4] = {bv1.x, bv1.y, bv1.z, bv1.w};
    float bb2[4] = {bv2.x, bv2.y, bv2.z, bv2.w};

    const int cbase = bn + tx * 4;
    float sx[4] = {0.f, 0.f, 0.f, 0.f}, sy[4] = {0.f, 0.f, 0.f, 0.f};

#pragma unroll
    for (int j = 0; j < 8; j++) {
        const int row = bm + ty * 8 + j;
        float4 ox, oy;
        float xs[4], ys[4];
#pragma unroll
        for (int l = 0; l < 4; l++) {
            const float h1 = acc1[j][l] + bb1[l];
            const float h2 = acc2[j][l] + bb2[l];
            const float rad = fabsf(h1) + 0.1f;
            float s, c;
            sincosf(PI_F * h2, &s, &c);
            xs[l] = rad * c; ys[l] = rad * s;
            sx[l] += xs[l];  sy[l] += ys[l];
        }
        ox.x = xs[0]; ox.y = xs[1]; ox.z = xs[2]; ox.w = xs[3];
        oy.x = ys[0]; oy.y = ys[1]; oy.z = ys[2]; oy.w = ys[3];
        *(float4*)(g_xc + (size_t)row * 256 + cbase) = ox;
        *(float4*)(g_yc + (size_t)row * 256 + cbase) = oy;
    }

    // Reduce sums over the 8 ty-rows of each 64-row chunk half (reuse As as scratch: 8KB)
    float* sred = (float*)As;
    // last loop iteration ended with __syncthreads(): all smem reads done
#pragma unroll
    for (int l = 0; l < 4; l++) { sred[tid * 8 + l] = sx[l]; sred[tid * 8 + 4 + l] = sy[l]; }
    __syncthreads();

    if ((ty & 7) == 0) {        // ty == 0 (chunk half 0) or ty == 8 (chunk half 1)
        const int b = bm >> 10;
        const int chunk = ((bm & 1023) >> 6) + (ty >> 3);
        float tx4[4] = {0.f, 0.f, 0.f, 0.f}, ty4[4] = {0.f, 0.f, 0.f, 0.f};
#pragma unroll
        for (int u = 0; u < 8; u++) {
            const int src = ((ty + u) * 16 + tx) * 8;
#pragma unroll
            for (int l = 0; l < 4; l++) { tx4[l] += sred[src + l]; ty4[l] += sred[src + 4 + l]; }
        }
#pragma unroll
        for (int l = 0; l < 4; l++) {
            g_xp[chunk * BD + b * DD + cbase + l] = tx4[l];
            g_yp[chunk * BD + b * DD + cbase + l] = ty4[l];
        }
    }
}

// ---------------- 2) all 8 KAN layers in ONE kernel (per-(b,d) independent chain) ----------------
// 64-thread blocks so the grid (256 blocks) spreads across all 148 SMs
// (the 64x256 shape left 84 SMs idle: occ 12.6%).
__global__ __launch_bounds__(64) void k_mlp_all(const float* __restrict__ mw1, const float* __restrict__ mb1,
                                                const float* __restrict__ mw2, const float* __restrict__ mb2,
                                                const float* __restrict__ pw1, const float* __restrict__ pb1,
                                                const float* __restrict__ pw2, const float* __restrict__ pb2) {
    __shared__ float w[NLAYERS * WSTRIDE];
    const int t = threadIdx.x;

    for (int idx = t; idx < NLAYERS * WSTRIDE; idx += 64) {
        const int l = idx / WSTRIDE;
        const int o = idx - l * WSTRIDE;
        float v = 0.0f;
        if      (o < 32)  v = mw1[l * 32 + o];
        else if (o < 64)  v = mb1[l * 32 + (o - 32)];
        else if (o < 96)  v = mw2[l * 32 + (o - 64)];
        else if (o < 160) v = pw1[l * 64 + (o - 96)];     // [0..31]=sin row, [32..63]=cos row
        else if (o < 192) v = pb1[l * 32 + (o - 160)];
        else if (o < 256) v = pw2[l * 64 + (o - 192)];    // interleaved [j*2 + {0,1}]
        else if (o == 256) v = mb2[l];
        else if (o == 257) v = pb2[2 * l];
        else if (o == 258) v = pb2[2 * l + 1];
        w[idx] = v;
    }
    __syncthreads();

    const int k = blockIdx.x * 64 + t;   // (b,d) flat
    float xs = 0.0f, ys = 0.0f;
#pragma unroll
    for (int c = 0; c < NCHUNK; c++) { xs += g_xp[c * BD + k]; ys += g_yp[c * BD + k]; }
    float xm = xs * (1.0f / SS), ym = ys * (1.0f / SS);
    float DX = 0.0f, DY = 0.0f;

    for (int l = 0; l < NLAYERS; l++) {
        const float* wl = w + l * WSTRIDE;
        const float ragg  = sqrtf(xm * xm + ym * ym + EPSF);
        const float thagg = atan2f(ym, xm);

        // magnitude MLP (1 -> 32 -> 1) in log space
        const float logr = logf(ragg + EPSF);
        float acc = 0.0f;
#pragma unroll
        for (int j = 0; j < 32; j++) {
            const float u = fmaf(logr, wl[j], wl[32 + j]);
            acc = fmaf(gelu_exact(u), wl[64 + j], acc);
        }
        const float rt = expf(acc + wl[256]);

        // phase MLP (2 -> 32 -> 2) on (sin, cos)
        float s0, c0;
        sincosf(thagg, &s0, &c0);
        float p0 = 0.0f, p1 = 0.0f;
#pragma unroll
        for (int j = 0; j < 32; j++) {
            const float u = fmaf(s0, wl[96 + j], fmaf(c0, wl[128 + j], wl[160 + j]));
            const float g = gelu_exact(u);
            p0 = fmaf(g, wl[192 + 2 * j],     p0);
            p1 = fmaf(g, wl[192 + 2 * j + 1], p1);
        }
        p0 += wl[257]; p1 += wl[258];
        const float nrm = sqrtf(p0 * p0 + p1 * p1 + EPSF);
        const float tht = atan2f(p0 / nrm, p1 / nrm);
        float sd, cd;
        sincosf(tht, &sd, &cd);
        const float dx = rt * cd, dy = rt * sd;

        xm += dx; ym += dy;
        DX += dx; DY += dy;
    }
    g_dx[k] = DX;
    g_dy[k] = DY;
}

// ---------------- 3) final pass: r = sqrt((xc0+DX)^2 + (yc0+DY)^2 + eps), chunk sums ----------------
__global__ __launch_bounds__(256) void k_final() {
    __shared__ float sh[4][64][4];
    const int b = blockIdx.y, chunk = blockIdx.x, t = threadIdx.x;
    const int c4 = t & 63, rsub = t >> 6;
    const int dbase = c4 * 4;

    const float4 dxv = *(const float4*)(g_dx + b * DD + dbase);
    const float4 dyv = *(const float4*)(g_dy + b * DD + dbase);

    float s[4] = {0.f, 0.f, 0.f, 0.f};
    const size_t rowbase = (size_t)b * SS + (size_t)chunk * 64;
#pragma unroll 4
    for (int i = 0; i < 16; i++) {
        const size_t idx = (rowbase + rsub + 4 * i) * DD + dbase;
        const float4 xv = *(const float4*)(g_xc + idx);
        const float4 yv = *(const float4*)(g_yc + idx);
        float x0 = xv.x + dxv.x, y0 = yv.x + dyv.x;
        float x1 = xv.y + dxv.y, y1 = yv.y + dyv.y;
        float x2 = xv.z + dxv.z, y2 = yv.z + dyv.z;
        float x3 = xv.w + dxv.w, y3 = yv.w + dyv.w;
        s[0] += sqrtf(fmaf(x0, x0, fmaf(y0, y0, EPSF)));
        s[1] += sqrtf(fmaf(x1, x1, fmaf(y1, y1, EPSF)));
        s[2] += sqrtf(fmaf(x2, x2, fmaf(y2, y2, EPSF)));
        s[3] += sqrtf(fmaf(x3, x3, fmaf(y3, y3, EPSF)));
    }
#pragma unroll
    for (int j = 0; j < 4; j++) sh[rsub][c4][j] = s[j];
    __syncthreads();
    if (rsub == 0) {
#pragma unroll
        for (int j = 0; j < 4; j++) {
            float tot = sh[0][c4][j] + sh[1][c4][j] + sh[2][c4][j] + sh[3][c4][j];
            g_xp[chunk * BD + b * DD + dbase + j] = tot;
        }
    }
}

// ---------------- 4) classifier (parallelized hidden layer) ----------------
__global__ __launch_bounds__(256) void k_cls(const float* __restrict__ w1, const float* __restrict__ b1,
                                             const float* __restrict__ w2, const float* __restrict__ b2,
                                             float* __restrict__ out) {
    __shared__ float p[DD];
    __shared__ float hp[8][33];
    __shared__ float h[KANH];
    const int b = blockIdx.x, t = threadIdx.x;
    float s = 0.0f;
#pragma unroll
    for (int c = 0; c < NCHUNK; c++) s += g_xp[c * BD + b * DD + t];
    p[t] = s * (1.0f / SS);
    __syncthreads();
    {
        const int jj = t & 31, sl = t >> 5;   // 8 slices of the 256-dot per hidden unit
        float a = 0.0f;
#pragma unroll
        for (int q = 0; q < 32; q++) {
            const int d2 = sl * 32 + q;
            a = fmaf(p[d2], w1[d2 * KANH + jj], a);
        }
        hp[sl][jj] = a;
    }
    __syncthreads();
    if (t < KANH) {
        float a = b1[t];
#pragma unroll
        for (int s8 = 0; s8 < 8; s8++) a += hp[s8][t];
        h[t] = gelu_exact(a);
    }
    __syncthreads();
    for (int c = t; c < NCLS; c += 256) {
        float a = b2[c];
#pragma unroll
        for (int jj = 0; jj < KANH; jj++) a = fmaf(h[jj], w2[jj * NCLS + c], a);
        out[b * NCLS + c] = a;
    }
}

// ---------------- launch ----------------
extern "C" void kernel_launch(void* const* d_in, const int* in_sizes, int n_in,
                              void* d_out, int out_size) {
    const float* x   = (const float*)d_in[0];
    const float* ew  = (const float*)d_in[1];
    const float* eb  = (const float*)d_in[2];
    const float* mw1 = (const float*)d_in[3];
    const float* mb1 = (const float*)d_in[4];
    const float* mw2 = (const float*)d_in[5];
    const float* mb2 = (const float*)d_in[6];
    const float* pw1 = (const float*)d_in[7];
    const float* pb1 = (const float*)d_in[8];
    const float* pw2 = (const float*)d_in[9];
    const float* pb2 = (const float*)d_in[10];
    const float* cw1 = (const float*)d_in[11];
    const float* cb1 = (const float*)d_in[12];
    const float* cw2 = (const float*)d_in[13];
    const float* cb2 = (const float*)d_in[14];
    float* out = (float*)d_out;

    dim3 ggrid(DD / 64, (BB * SS) / 128);    // (4, 512) — each block does both h1/h2 halves
    k_embed_fused<<<ggrid, 256>>>(x, ew, eb);

    k_mlp_all<<<BD / 64, 64>>>(mw1, mb1, mw2, mb2, pw1, pb1, pw2, pb2);

    dim3 fgrid(NCHUNK, BB);                  // (16, 64)
    k_final<<<fgrid, 256>>>();

    k_cls<<<BB, 256>>>(cw1, cb1, cw2, cb2, out);
}

// round 14
// speedup vs baseline: 1.7481x; 1.3603x over previous
#include <cuda_runtime.h>
#include <cuda_bf16.h>
#include <math.h>
#include <stdint.h>

#define BB 64
#define SS 1024
#define DD 256
#define NLAYERS 8
#define KANH 32
#define NCLS 1000
#define EPSF 1e-8f
#define PI_F 3.14159265358979323846f
#define NCHUNK 16
#define BD (BB*DD)
#define WSTRIDE 260

// ---------------- persistent device scratch ----------------
__device__ float g_xc[BB*SS*DD];
__device__ float g_yc[BB*SS*DD];
__device__ float g_xp[NCHUNK*BD];
__device__ float g_yp[NCHUNK*BD];
__device__ float g_dx[BD];
__device__ float g_dy[BD];
__device__ __nv_bfloat16 g_ah[BB*SS*DD];   // A hi
__device__ __nv_bfloat16 g_al[BB*SS*DD];   // A lo
__device__ __nv_bfloat16 g_bhT[512*256];   // W hi, transposed [n][k]
__device__ __nv_bfloat16 g_blT[512*256];   // W lo, transposed [n][k]

__device__ __forceinline__ float gelu_exact(float v) {
    return 0.5f * v * (1.0f + erff(v * 0.70710678118654752440f));
}
__device__ __forceinline__ uint32_t smem_u32(const void* p) {
    uint32_t a;
    asm("{ .reg .u64 t; cvta.to.shared.u64 t, %1; cvt.u32.u64 %0, t; }" : "=r"(a) : "l"(p));
    return a;
}
__device__ __forceinline__ void mma16816(float c[4], const uint32_t a[4], const uint32_t b[2]) {
    asm volatile("mma.sync.aligned.m16n8k16.row.col.f32.bf16.bf16.f32 "
                 "{%0,%1,%2,%3}, {%4,%5,%6,%7}, {%8,%9}, {%0,%1,%2,%3};"
                 : "+f"(c[0]), "+f"(c[1]), "+f"(c[2]), "+f"(c[3])
                 : "r"(a[0]), "r"(a[1]), "r"(a[2]), "r"(a[3]), "r"(b[0]), "r"(b[1]));
}

// ---------------- split-bf16 conversion kernels ----------------
__global__ __launch_bounds__(256) void k_cvt_a(const float* __restrict__ x) {
    const size_t i = ((size_t)blockIdx.x * 256 + threadIdx.x) * 4;
    float4 v = *(const float4*)(x + i);
    __nv_bfloat16 h0 = __float2bfloat16(v.x);
    __nv_bfloat16 h1 = __float2bfloat16(v.y);
    __nv_bfloat16 h2 = __float2bfloat16(v.z);
    __nv_bfloat16 h3 = __float2bfloat16(v.w);
    g_ah[i+0] = h0; g_ah[i+1] = h1; g_ah[i+2] = h2; g_ah[i+3] = h3;
    g_al[i+0] = __float2bfloat16(v.x - __bfloat162float(h0));
    g_al[i+1] = __float2bfloat16(v.y - __bfloat162float(h1));
    g_al[i+2] = __float2bfloat16(v.z - __bfloat162float(h2));
    g_al[i+3] = __float2bfloat16(v.w - __bfloat162float(h3));
}
__global__ __launch_bounds__(256) void k_cvt_w(const float* __restrict__ W) {
    const int idx = blockIdx.x * 256 + threadIdx.x;   // [n][k], 512*256
    const int n = idx >> 8, k = idx & 255;
    const float v = W[k * 512 + n];
    __nv_bfloat16 h = __float2bfloat16(v);
    g_bhT[idx] = h;
    g_blT[idx] = __float2bfloat16(v - __bfloat162float(h));
}

// ---------------- mma.sync embed GEMM + fused polar epilogue ----------------
// Block: 128 rows x 128 cols (64 h1-cols + 64 h2-cols of d-group j).
// 8 warps: wm = w&3 -> 32-row slice; half = w>>2 -> h1 (0) or h2 (1).
// K=256 in 32-chunks, 2-stage cp.async double buffer. 4-pass split-bf16.

#define A_STRIDE 40                       // bf16 per smem row (32 + 8 pad)
#define ARR_BYTES (128*A_STRIDE*2)        // 10240 per array
#define STAGE_BYTES (4*ARR_BYTES)         // Ah,Al,Bh,Bl = 40960
#define GSMEM_TOT (2*STAGE_BYTES)         // 81920 (>= epilogue stage 33280)
#define STG_STRIDE 65

__device__ __forceinline__ void fill_stage(uint32_t sbase, int t, int bm, int j, int s, int kc) {
    const uint32_t base = sbase + (uint32_t)s * STAGE_BYTES;
#pragma unroll
    for (int it = 0; it < 8; it++) {
        const int c = it * 256 + t;            // 0..2047
        const int arr = c >> 9, rem = c & 511;
        const int row = rem >> 2, seg = rem & 3;
        const __nv_bfloat16* src;
        if (arr == 0)      src = g_ah + (size_t)(bm + row) * 256 + kc * 32 + seg * 8;
        else if (arr == 1) src = g_al + (size_t)(bm + row) * 256 + kc * 32 + seg * 8;
        else {
            const int nglob = (row < 64) ? (j * 64 + row) : (256 + j * 64 + (row - 64));
            src = ((arr == 2) ? g_bhT : g_blT) + nglob * 256 + kc * 32 + seg * 8;
        }
        const uint32_t dst = base + (uint32_t)arr * ARR_BYTES + (uint32_t)row * 80 + (uint32_t)seg * 16;
        asm volatile("cp.async.cg.shared.global [%0], [%1], 16;" :: "r"(dst), "l"(src) : "memory");
    }
    asm volatile("cp.async.commit_group;" ::: "memory");
}

__global__ __launch_bounds__(256, 2) void k_gemm(const float* __restrict__ bias) {
    extern __shared__ char smem[];
    const uint32_t sbase = smem_u32(smem);
    const int t = threadIdx.x;
    const int lane = t & 31, w = t >> 5;
    const int g = lane >> 2, tg = lane & 3;
    const int wm = w & 3, half = w >> 2;
    const int j = blockIdx.x, mtile = blockIdx.y;
    const int bm = mtile * 128;
    const int b = bm >> 10;
    const int chunkbase = (bm & 1023) >> 6;

    __shared__ float sumx[256], sumy[256];
    __shared__ float sb1[64], sb2[64];
    if (t < 64) { sb1[t] = bias[j * 64 + t]; sb2[t] = bias[256 + j * 64 + t]; }

    float acc[2][8][4];
#pragma unroll
    for (int mt = 0; mt < 2; mt++)
#pragma unroll
        for (int nt = 0; nt < 8; nt++)
#pragma unroll
            for (int c = 0; c < 4; c++) acc[mt][nt][c] = 0.0f;

    fill_stage(sbase, t, bm, j, 0, 0);

    for (int kc = 0; kc < 8; kc++) {
        const int cur = kc & 1;
        if (kc < 7) {
            fill_stage(sbase, t, bm, j, cur ^ 1, kc + 1);
            asm volatile("cp.async.wait_group 1;" ::: "memory");
        } else {
            asm volatile("cp.async.wait_group 0;" ::: "memory");
        }
        __syncthreads();

        const __nv_bfloat16* pAh = (const __nv_bfloat16*)(smem + cur * STAGE_BYTES);
        const __nv_bfloat16* pAl = (const __nv_bfloat16*)(smem + cur * STAGE_BYTES + ARR_BYTES);
        const __nv_bfloat16* pBh = (const __nv_bfloat16*)(smem + cur * STAGE_BYTES + 2 * ARR_BYTES);
        const __nv_bfloat16* pBl = (const __nv_bfloat16*)(smem + cur * STAGE_BYTES + 3 * ARR_BYTES);

#pragma unroll
        for (int kk = 0; kk < 2; kk++) {
            const int kb = kk * 16 + tg * 2;
            uint32_t ah[2][4], al[2][4];
#pragma unroll
            for (int mt = 0; mt < 2; mt++) {
                const __nv_bfloat16* p = pAh + (wm * 32 + mt * 16 + g) * A_STRIDE + kb;
                ah[mt][0] = *(const uint32_t*)(p);
                ah[mt][1] = *(const uint32_t*)(p + 8 * A_STRIDE);
                ah[mt][2] = *(const uint32_t*)(p + 8);
                ah[mt][3] = *(const uint32_t*)(p + 8 * A_STRIDE + 8);
                const __nv_bfloat16* q = pAl + (wm * 32 + mt * 16 + g) * A_STRIDE + kb;
                al[mt][0] = *(const uint32_t*)(q);
                al[mt][1] = *(const uint32_t*)(q + 8 * A_STRIDE);
                al[mt][2] = *(const uint32_t*)(q + 8);
                al[mt][3] = *(const uint32_t*)(q + 8 * A_STRIDE + 8);
            }
#pragma unroll
            for (int nt = 0; nt < 8; nt++) {
                const __nv_bfloat16* p = pBh + (half * 64 + nt * 8 + g) * A_STRIDE + kb;
                const __nv_bfloat16* q = pBl + (half * 64 + nt * 8 + g) * A_STRIDE + kb;
                uint32_t bh[2], bl[2];
                bh[0] = *(const uint32_t*)(p); bh[1] = *(const uint32_t*)(p + 8);
                bl[0] = *(const uint32_t*)(q); bl[1] = *(const uint32_t*)(q + 8);
                mma16816(acc[0][nt], ah[0], bh);
                mma16816(acc[1][nt], ah[1], bh);
                mma16816(acc[0][nt], al[0], bh);
                mma16816(acc[1][nt], al[1], bh);
                mma16816(acc[0][nt], ah[0], bl);
                mma16816(acc[1][nt], ah[1], bl);
                mma16816(acc[0][nt], al[0], bl);
                mma16816(acc[1][nt], al[1], bl);
            }
        }
        __syncthreads();
    }

    // -------- epilogue: h2 staged through smem, polar, writes, chunk sums --------
    float* stage = (float*)smem;   // 128 x STG_STRIDE floats (overlays mainloop smem)
    if (half == 1) {
#pragma unroll
        for (int mt = 0; mt < 2; mt++)
#pragma unroll
            for (int nt = 0; nt < 8; nt++) {
                const int r0 = wm * 32 + mt * 16 + g;
                const int col = nt * 8 + tg * 2;
                stage[r0 * STG_STRIDE + col]           = acc[mt][nt][0] + sb2[col];
                stage[r0 * STG_STRIDE + col + 1]       = acc[mt][nt][1] + sb2[col + 1];
                stage[(r0 + 8) * STG_STRIDE + col]     = acc[mt][nt][2] + sb2[col];
                stage[(r0 + 8) * STG_STRIDE + col + 1] = acc[mt][nt][3] + sb2[col + 1];
            }
    }
    __syncthreads();
    if (half == 0) {
        float csx[16], csy[16];
#pragma unroll
        for (int q = 0; q < 16; q++) { csx[q] = 0.0f; csy[q] = 0.0f; }
#pragma unroll
        for (int mt = 0; mt < 2; mt++)
#pragma unroll
            for (int nt = 0; nt < 8; nt++) {
                const int col = nt * 8 + tg * 2;
                const int d = j * 64 + col;
                const float b0 = sb1[col], b1v = sb1[col + 1];
#pragma unroll
                for (int rh = 0; rh < 2; rh++) {
                    const int row = wm * 32 + mt * 16 + g + rh * 8;
                    const float h1a = acc[mt][nt][rh * 2 + 0] + b0;
                    const float h1b = acc[mt][nt][rh * 2 + 1] + b1v;
                    const float h2a = stage[row * STG_STRIDE + col];
                    const float h2b = stage[row * STG_STRIDE + col + 1];
                    const float ra = fabsf(h1a) + 0.1f;
                    const float rb = fabsf(h1b) + 0.1f;
                    float sa, ca, sb_, cb;
                    sincosf(PI_F * h2a, &sa, &ca);
                    sincosf(PI_F * h2b, &sb_, &cb);
                    const float xa = ra * ca, ya = ra * sa;
                    const float xb = rb * cb, yb = rb * sb_;
                    float2 xv; xv.x = xa; xv.y = xb;
                    float2 yv; yv.x = ya; yv.y = yb;
                    *(float2*)(g_xc + (size_t)(bm + row) * 256 + d) = xv;
                    *(float2*)(g_yc + (size_t)(bm + row) * 256 + d) = yv;
                    csx[nt * 2]     += xa;  csx[nt * 2 + 1] += xb;
                    csy[nt * 2]     += ya;  csy[nt * 2 + 1] += yb;
                }
            }
#pragma unroll
        for (int off = 4; off <= 16; off <<= 1)
#pragma unroll
            for (int q = 0; q < 16; q++) {
                csx[q] += __shfl_xor_sync(0xffffffffu, csx[q], off);
                csy[q] += __shfl_xor_sync(0xffffffffu, csy[q], off);
            }
        if (lane < 4) {
#pragma unroll
            for (int nt = 0; nt < 8; nt++) {
#pragma unroll
                for (int e = 0; e < 2; e++) {
                    const int col = nt * 8 + tg * 2 + e;
                    sumx[wm * 64 + col] = csx[nt * 2 + e];
                    sumy[wm * 64 + col] = csy[nt * 2 + e];
                }
            }
        }
    }
    __syncthreads();
    if (t < 128) {        // 64-row chunk sums: warp-row pairs (0,1) and (2,3)
        const int chunk = t >> 6, col = t & 63;
        const float xs = sumx[(chunk * 2) * 64 + col] + sumx[(chunk * 2 + 1) * 64 + col];
        const float ys = sumy[(chunk * 2) * 64 + col] + sumy[(chunk * 2 + 1) * 64 + col];
        const int cg = chunkbase + chunk;
        const int d = j * 64 + col;
        g_xp[cg * BD + b * DD + d] = xs;
        g_yp[cg * BD + b * DD + d] = ys;
    }
}

// ---------------- all 8 KAN layers in ONE kernel ----------------
__global__ __launch_bounds__(64) void k_mlp_all(const float* __restrict__ mw1, const float* __restrict__ mb1,
                                                const float* __restrict__ mw2, const float* __restrict__ mb2,
                                                const float* __restrict__ pw1, const float* __restrict__ pb1,
                                                const float* __restrict__ pw2, const float* __restrict__ pb2) {
    __shared__ float w[NLAYERS * WSTRIDE];
    const int t = threadIdx.x;
    for (int idx = t; idx < NLAYERS * WSTRIDE; idx += 64) {
        const int l = idx / WSTRIDE;
        const int o = idx - l * WSTRIDE;
        float v = 0.0f;
        if      (o < 32)  v = mw1[l * 32 + o];
        else if (o < 64)  v = mb1[l * 32 + (o - 32)];
        else if (o < 96)  v = mw2[l * 32 + (o - 64)];
        else if (o < 160) v = pw1[l * 64 + (o - 96)];
        else if (o < 192) v = pb1[l * 32 + (o - 160)];
        else if (o < 256) v = pw2[l * 64 + (o - 192)];
        else if (o == 256) v = mb2[l];
        else if (o == 257) v = pb2[2 * l];
        else if (o == 258) v = pb2[2 * l + 1];
        w[idx] = v;
    }
    __syncthreads();

    const int k = blockIdx.x * 64 + t;
    float xs = 0.0f, ys = 0.0f;
#pragma unroll
    for (int c = 0; c < NCHUNK; c++) { xs += g_xp[c * BD + k]; ys += g_yp[c * BD + k]; }
    float xm = xs * (1.0f / SS), ym = ys * (1.0f / SS);
    float DX = 0.0f, DY = 0.0f;

    for (int l = 0; l < NLAYERS; l++) {
        const float* wl = w + l * WSTRIDE;
        const float ragg  = sqrtf(xm * xm + ym * ym + EPSF);
        const float thagg = atan2f(ym, xm);
        const float logr = logf(ragg + EPSF);
        float acc = 0.0f;
#pragma unroll
        for (int jj = 0; jj < 32; jj++) {
            const float u = fmaf(logr, wl[jj], wl[32 + jj]);
            acc = fmaf(gelu_exact(u), wl[64 + jj], acc);
        }
        const float rt = expf(acc + wl[256]);
        float s0, c0;
        sincosf(thagg, &s0, &c0);
        float p0 = 0.0f, p1 = 0.0f;
#pragma unroll
        for (int jj = 0; jj < 32; jj++) {
            const float u = fmaf(s0, wl[96 + jj], fmaf(c0, wl[128 + jj], wl[160 + jj]));
            const float g = gelu_exact(u);
            p0 = fmaf(g, wl[192 + 2 * jj],     p0);
            p1 = fmaf(g, wl[192 + 2 * jj + 1], p1);
        }
        p0 += wl[257]; p1 += wl[258];
        const float nrm = sqrtf(p0 * p0 + p1 * p1 + EPSF);
        const float tht = atan2f(p0 / nrm, p1 / nrm);
        float sd, cd;
        sincosf(tht, &sd, &cd);
        const float dx = rt * cd, dy = rt * sd;
        xm += dx; ym += dy;
        DX += dx; DY += dy;
    }
    g_dx[k] = DX;
    g_dy[k] = DY;
}

// ---------------- final pass: r = sqrt((xc0+DX)^2 + (yc0+DY)^2 + eps), chunk sums ----------------
__global__ __launch_bounds__(256) void k_final() {
    __shared__ float sh[4][64][4];
    const int b = blockIdx.y, chunk = blockIdx.x, t = threadIdx.x;
    const int c4 = t & 63, rsub = t >> 6;
    const int dbase = c4 * 4;

    const float4 dxv = *(const float4*)(g_dx + b * DD + dbase);
    const float4 dyv = *(const float4*)(g_dy + b * DD + dbase);

    float s[4] = {0.f, 0.f, 0.f, 0.f};
    const size_t rowbase = (size_t)b * SS + (size_t)chunk * 64;
#pragma unroll 4
    for (int i = 0; i < 16; i++) {
        const size_t idx = (rowbase + rsub + 4 * i) * DD + dbase;
        const float4 xv = *(const float4*)(g_xc + idx);
        const float4 yv = *(const float4*)(g_yc + idx);
        float x0 = xv.x + dxv.x, y0 = yv.x + dyv.x;
        float x1 = xv.y + dxv.y, y1 = yv.y + dyv.y;
        float x2 = xv.z + dxv.z, y2 = yv.z + dyv.z;
        float x3 = xv.w + dxv.w, y3 = yv.w + dyv.w;
        s[0] += sqrtf(fmaf(x0, x0, fmaf(y0, y0, EPSF)));
        s[1] += sqrtf(fmaf(x1, x1, fmaf(y1, y1, EPSF)));
        s[2] += sqrtf(fmaf(x2, x2, fmaf(y2, y2, EPSF)));
        s[3] += sqrtf(fmaf(x3, x3, fmaf(y3, y3, EPSF)));
    }
#pragma unroll
    for (int jj = 0; jj < 4; jj++) sh[rsub][c4][jj] = s[jj];
    __syncthreads();
    if (rsub == 0) {
#pragma unroll
        for (int jj = 0; jj < 4; jj++) {
            float tot = sh[0][c4][jj] + sh[1][c4][jj] + sh[2][c4][jj] + sh[3][c4][jj];
            g_xp[chunk * BD + b * DD + dbase + jj] = tot;
        }
    }
}

// ---------------- classifier (grid-parallel over class groups) ----------------
__global__ __launch_bounds__(256) void k_cls(const float* __restrict__ w1, const float* __restrict__ b1,
                                             const float* __restrict__ w2, const float* __restrict__ b2,
                                             float* __restrict__ out) {
    __shared__ float p[DD];
    __shared__ float hp[8][33];
    __shared__ float h[KANH];
    const int b = blockIdx.x, cg = blockIdx.y, t = threadIdx.x;
    float s = 0.0f;
#pragma unroll
    for (int c = 0; c < NCHUNK; c++) s += g_xp[c * BD + b * DD + t];
    p[t] = s * (1.0f / SS);
    __syncthreads();
    {
        const int jj = t & 31, sl = t >> 5;
        float a = 0.0f;
#pragma unroll
        for (int q = 0; q < 32; q++) {
            const int d2 = sl * 32 + q;
            a = fmaf(p[d2], w1[d2 * KANH + jj], a);
        }
        hp[sl][jj] = a;
    }
    __syncthreads();
    if (t < KANH) {
        float a = b1[t];
#pragma unroll
        for (int s8 = 0; s8 < 8; s8++) a += hp[s8][t];
        h[t] = gelu_exact(a);
    }
    __syncthreads();
    const int c = cg * 250 + t;
    if (t < 250) {
        float a = b2[c];
#pragma unroll
        for (int jj = 0; jj < KANH; jj++) a = fmaf(h[jj], w2[jj * NCLS + c], a);
        out[b * NCLS + c] = a;
    }
}

// ---------------- launch ----------------
extern "C" void kernel_launch(void* const* d_in, const int* in_sizes, int n_in,
                              void* d_out, int out_size) {
    const float* x   = (const float*)d_in[0];
    const float* ew  = (const float*)d_in[1];
    const float* eb  = (const float*)d_in[2];
    const float* mw1 = (const float*)d_in[3];
    const float* mb1 = (const float*)d_in[4];
    const float* mw2 = (const float*)d_in[5];
    const float* mb2 = (const float*)d_in[6];
    const float* pw1 = (const float*)d_in[7];
    const float* pb1 = (const float*)d_in[8];
    const float* pw2 = (const float*)d_in[9];
    const float* pb2 = (const float*)d_in[10];
    const float* cw1 = (const float*)d_in[11];
    const float* cb1 = (const float*)d_in[12];
    const float* cw2 = (const float*)d_in[13];
    const float* cb2 = (const float*)d_in[14];
    float* out = (float*)d_out;

    cudaFuncSetAttribute(k_gemm, cudaFuncAttributeMaxDynamicSharedMemorySize, GSMEM_TOT);

    k_cvt_a<<<(BB * SS * DD) / (256 * 4), 256>>>(x);
    k_cvt_w<<<512, 256>>>(ew);

    dim3 ggrid(4, 512);                      // x = d-group j (L2 reuse of A across j), y = mtile
    k_gemm<<<ggrid, 256, GSMEM_TOT>>>(eb);

    k_mlp_all<<<BD / 64, 64>>>(mw1, mb1, mw2, mb2, pw1, pb1, pw2, pb2);

    dim3 fgrid(NCHUNK, BB);
    k_final<<<fgrid, 256>>>();

    dim3 cgrid(BB, 4);
    k_cls<<<cgrid, 256>>>(cw1, cb1, cw2, cb2, out);
}

// round 15
// speedup vs baseline: 1.8412x; 1.0532x over previous
#include <cuda_runtime.h>
#include <cuda_bf16.h>
#include <cuda_fp16.h>
#include <math.h>
#include <stdint.h>

#define BB 64
#define SS 1024
#define DD 256
#define NLAYERS 8
#define KANH 32
#define NCLS 1000
#define EPSF 1e-8f
#define PI_F 3.14159265358979323846f
#define NCHUNK 16
#define BD (BB*DD)
#define WSTRIDE 260

// ---------------- persistent device scratch ----------------
__device__ __half g_xc[BB*SS*DD];          // xc0 (fp16 — only feeds final pooled mean)
__device__ __half g_yc[BB*SS*DD];
__device__ float g_xp[NCHUNK*BD];          // fp32 chunk sums (feed the sensitive KAN chain)
__device__ float g_yp[NCHUNK*BD];
__device__ float g_dx[BD];
__device__ float g_dy[BD];
__device__ __nv_bfloat16 g_bhT[512*256];   // W hi, transposed [n][k]
__device__ __nv_bfloat16 g_blT[512*256];   // W lo, transposed [n][k]

__device__ __forceinline__ float gelu_exact(float v) {
    return 0.5f * v * (1.0f + erff(v * 0.70710678118654752440f));
}
__device__ __forceinline__ uint32_t smem_u32(const void* p) {
    uint32_t a;
    asm("{ .reg .u64 t; cvta.to.shared.u64 t, %1; cvt.u32.u64 %0, t; }" : "=r"(a) : "l"(p));
    return a;
}
__device__ __forceinline__ void mma16816(float c[4], const uint32_t a[4], const uint32_t b[2]) {
    asm volatile("mma.sync.aligned.m16n8k16.row.col.f32.bf16.bf16.f32 "
                 "{%0,%1,%2,%3}, {%4,%5,%6,%7}, {%8,%9}, {%0,%1,%2,%3};"
                 : "+f"(c[0]), "+f"(c[1]), "+f"(c[2]), "+f"(c[3])
                 : "r"(a[0]), "r"(a[1]), "r"(a[2]), "r"(a[3]), "r"(b[0]), "r"(b[1]));
}

// ---------------- W split conversion (A converts inline in k_gemm) ----------------
__global__ __launch_bounds__(256) void k_cvt_w(const float* __restrict__ W) {
    const int idx = blockIdx.x * 256 + threadIdx.x;   // [n][k], 512*256
    const int n = idx >> 8, k = idx & 255;
    const float v = W[k * 512 + n];
    __nv_bfloat16 h = __float2bfloat16(v);
    g_bhT[idx] = h;
    g_blT[idx] = __float2bfloat16(v - __bfloat162float(h));
}

// ---------------- mma.sync embed GEMM + fused polar epilogue ----------------
// Block: 128 rows x 128 cols (64 h1-cols + 64 h2-cols of d-group j).
// 8 warps: wm = w&3 -> 32-row slice; half = w>>2 -> h1 (0) or h2 (1).
// K=256 in 32-chunks, 2-stage double buffer: B via cp.async, A via reg-prefetch
// LDG fp32 + inline hi/lo bf16 conversion. 4-pass split-bf16.

#define A_STRIDE 40                       // bf16 per smem row (32 + 8 pad)
#define ARR_BYTES (128*A_STRIDE*2)        // 10240 per array
#define STAGE_BYTES (4*ARR_BYTES)         // Ah,Al,Bh,Bl = 40960
#define GSMEM_TOT (2*STAGE_BYTES)         // 81920 (>= epilogue stage 33280)
#define STG_STRIDE 65

__device__ __forceinline__ void fill_B(uint32_t sbase, char* smem, int t, int j, int s, int kc) {
    const uint32_t base = sbase + (uint32_t)s * STAGE_BYTES + 2u * ARR_BYTES;
#pragma unroll
    for (int it = 0; it < 4; it++) {
        const int c = it * 256 + t;            // 0..1023
        const int arr = c >> 9, rem = c & 511;
        const int row = rem >> 2, seg = rem & 3;
        const int nglob = (row < 64) ? (j * 64 + row) : (256 + j * 64 + (row - 64));
        const __nv_bfloat16* src = ((arr == 0) ? g_bhT : g_blT) + nglob * 256 + kc * 32 + seg * 8;
        const uint32_t dst = base + (uint32_t)arr * ARR_BYTES + (uint32_t)row * 80 + (uint32_t)seg * 16;
        asm volatile("cp.async.cg.shared.global [%0], [%1], 16;" :: "r"(dst), "l"(src) : "memory");
    }
    asm volatile("cp.async.commit_group;" ::: "memory");
}

struct AReg { float4 v[4]; };

__device__ __forceinline__ void load_A(AReg& r, const float* __restrict__ A, int bm, int t, int kc) {
    const int row = t >> 1, ch = t & 1;
    const float* p = A + (size_t)(bm + row) * 256 + kc * 32 + ch * 16;
    r.v[0] = *(const float4*)(p);
    r.v[1] = *(const float4*)(p + 4);
    r.v[2] = *(const float4*)(p + 8);
    r.v[3] = *(const float4*)(p + 12);
}

__device__ __forceinline__ void store_A(const AReg& r, char* smem, int t, int s) {
    const int row = t >> 1, ch = t & 1;
    const float* f = (const float*)&r;
    uint32_t ah[8], al[8];
#pragma unroll
    for (int q = 0; q < 8; q++) {
        const float a0 = f[2 * q], a1 = f[2 * q + 1];
        __nv_bfloat16 h0 = __float2bfloat16(a0), h1 = __float2bfloat16(a1);
        __nv_bfloat16 l0 = __float2bfloat16(a0 - __bfloat162float(h0));
        __nv_bfloat16 l1 = __float2bfloat16(a1 - __bfloat162float(h1));
        ah[q] = (uint32_t)__bfloat16_as_ushort(h0) | ((uint32_t)__bfloat16_as_ushort(h1) << 16);
        al[q] = (uint32_t)__bfloat16_as_ushort(l0) | ((uint32_t)__bfloat16_as_ushort(l1) << 16);
    }
    char* base = smem + (size_t)s * STAGE_BYTES;
    const uint32_t off = (uint32_t)row * 80 + (uint32_t)ch * 32;
    *(uint4*)(base + off)                   = make_uint4(ah[0], ah[1], ah[2], ah[3]);
    *(uint4*)(base + off + 16)              = make_uint4(ah[4], ah[5], ah[6], ah[7]);
    *(uint4*)(base + ARR_BYTES + off)       = make_uint4(al[0], al[1], al[2], al[3]);
    *(uint4*)(base + ARR_BYTES + off + 16)  = make_uint4(al[4], al[5], al[6], al[7]);
}

__global__ __launch_bounds__(256, 2) void k_gemm(const float* __restrict__ A,
                                                 const float* __restrict__ bias) {
    extern __shared__ char smem[];
    const uint32_t sbase = smem_u32(smem);
    const int t = threadIdx.x;
    const int lane = t & 31, w = t >> 5;
    const int g = lane >> 2, tg = lane & 3;
    const int wm = w & 3, half = w >> 2;
    const int j = blockIdx.x, mtile = blockIdx.y;
    const int bm = mtile * 128;
    const int b = bm >> 10;
    const int chunkbase = (bm & 1023) >> 6;

    __shared__ float sumx[256], sumy[256];
    __shared__ float sb1[64], sb2[64];
    if (t < 64) { sb1[t] = bias[j * 64 + t]; sb2[t] = bias[256 + j * 64 + t]; }

    float acc[2][8][4];
#pragma unroll
    for (int mt = 0; mt < 2; mt++)
#pragma unroll
        for (int nt = 0; nt < 8; nt++)
#pragma unroll
            for (int c = 0; c < 4; c++) acc[mt][nt][c] = 0.0f;

    AReg areg;
    fill_B(sbase, smem, t, j, 0, 0);
    load_A(areg, A, bm, t, 0);
    store_A(areg, smem, t, 0);
    asm volatile("cp.async.wait_group 0;" ::: "memory");
    __syncthreads();

    for (int kc = 0; kc < 8; kc++) {
        const int cur = kc & 1;
        if (kc < 7) {
            fill_B(sbase, smem, t, j, cur ^ 1, kc + 1);
            load_A(areg, A, bm, t, kc + 1);
        }

        const __nv_bfloat16* pAh = (const __nv_bfloat16*)(smem + cur * STAGE_BYTES);
        const __nv_bfloat16* pAl = (const __nv_bfloat16*)(smem + cur * STAGE_BYTES + ARR_BYTES);
        const __nv_bfloat16* pBh = (const __nv_bfloat16*)(smem + cur * STAGE_BYTES + 2 * ARR_BYTES);
        const __nv_bfloat16* pBl = (const __nv_bfloat16*)(smem + cur * STAGE_BYTES + 3 * ARR_BYTES);

#pragma unroll
        for (int kk = 0; kk < 2; kk++) {
            const int kb = kk * 16 + tg * 2;
            uint32_t ah[2][4], al[2][4];
#pragma unroll
            for (int mt = 0; mt < 2; mt++) {
                const __nv_bfloat16* p = pAh + (wm * 32 + mt * 16 + g) * A_STRIDE + kb;
                ah[mt][0] = *(const uint32_t*)(p);
                ah[mt][1] = *(const uint32_t*)(p + 8 * A_STRIDE);
                ah[mt][2] = *(const uint32_t*)(p + 8);
                ah[mt][3] = *(const uint32_t*)(p + 8 * A_STRIDE + 8);
                const __nv_bfloat16* q = pAl + (wm * 32 + mt * 16 + g) * A_STRIDE + kb;
                al[mt][0] = *(const uint32_t*)(q);
                al[mt][1] = *(const uint32_t*)(q + 8 * A_STRIDE);
                al[mt][2] = *(const uint32_t*)(q + 8);
                al[mt][3] = *(const uint32_t*)(q + 8 * A_STRIDE + 8);
            }
#pragma unroll
            for (int nt = 0; nt < 8; nt++) {
                const __nv_bfloat16* p = pBh + (half * 64 + nt * 8 + g) * A_STRIDE + kb;
                const __nv_bfloat16* q = pBl + (half * 64 + nt * 8 + g) * A_STRIDE + kb;
                uint32_t bh[2], bl[2];
                bh[0] = *(const uint32_t*)(p); bh[1] = *(const uint32_t*)(p + 8);
                bl[0] = *(const uint32_t*)(q); bl[1] = *(const uint32_t*)(q + 8);
                mma16816(acc[0][nt], ah[0], bh);
                mma16816(acc[1][nt], ah[1], bh);
                mma16816(acc[0][nt], al[0], bh);
                mma16816(acc[1][nt], al[1], bh);
                mma16816(acc[0][nt], ah[0], bl);
                mma16816(acc[1][nt], ah[1], bl);
                mma16816(acc[0][nt], al[0], bl);
                mma16816(acc[1][nt], al[1], bl);
            }
        }

        if (kc < 7) {
            store_A(areg, smem, t, cur ^ 1);
            asm volatile("cp.async.wait_group 0;" ::: "memory");
        }
        __syncthreads();
    }

    // -------- epilogue: h2 staged through smem, polar, fp16 writes, chunk sums --------
    float* stage = (float*)smem;   // 128 x STG_STRIDE floats (overlays mainloop smem)
    if (half == 1) {
#pragma unroll
        for (int mt = 0; mt < 2; mt++)
#pragma unroll
            for (int nt = 0; nt < 8; nt++) {
                const int r0 = wm * 32 + mt * 16 + g;
                const int col = nt * 8 + tg * 2;
                stage[r0 * STG_STRIDE + col]           = acc[mt][nt][0] + sb2[col];
                stage[r0 * STG_STRIDE + col + 1]       = acc[mt][nt][1] + sb2[col + 1];
                stage[(r0 + 8) * STG_STRIDE + col]     = acc[mt][nt][2] + sb2[col];
                stage[(r0 + 8) * STG_STRIDE + col + 1] = acc[mt][nt][3] + sb2[col + 1];
            }
    }
    __syncthreads();
    if (half == 0) {
        float csx[16], csy[16];
#pragma unroll
        for (int q = 0; q < 16; q++) { csx[q] = 0.0f; csy[q] = 0.0f; }
#pragma unroll
        for (int mt = 0; mt < 2; mt++)
#pragma unroll
            for (int nt = 0; nt < 8; nt++) {
                const int col = nt * 8 + tg * 2;
                const int d = j * 64 + col;
                const float b0 = sb1[col], b1v = sb1[col + 1];
#pragma unroll
                for (int rh = 0; rh < 2; rh++) {
                    const int row = wm * 32 + mt * 16 + g + rh * 8;
                    const float h1a = acc[mt][nt][rh * 2 + 0] + b0;
                    const float h1b = acc[mt][nt][rh * 2 + 1] + b1v;
                    const float h2a = stage[row * STG_STRIDE + col];
                    const float h2b = stage[row * STG_STRIDE + col + 1];
                    const float ra = fabsf(h1a) + 0.1f;
                    const float rb = fabsf(h1b) + 0.1f;
                    float sa, ca, sb_, cb;
                    sincosf(PI_F * h2a, &sa, &ca);
                    sincosf(PI_F * h2b, &sb_, &cb);
                    const float xa = ra * ca, ya = ra * sa;
                    const float xb = rb * cb, yb = rb * sb_;
                    *(__half2*)(g_xc + (size_t)(bm + row) * 256 + d) = __floats2half2_rn(xa, xb);
                    *(__half2*)(g_yc + (size_t)(bm + row) * 256 + d) = __floats2half2_rn(ya, yb);
                    csx[nt * 2]     += xa;  csx[nt * 2 + 1] += xb;
                    csy[nt * 2]     += ya;  csy[nt * 2 + 1] += yb;
                }
            }
#pragma unroll
        for (int off = 4; off <= 16; off <<= 1)
#pragma unroll
            for (int q = 0; q < 16; q++) {
                csx[q] += __shfl_xor_sync(0xffffffffu, csx[q], off);
                csy[q] += __shfl_xor_sync(0xffffffffu, csy[q], off);
            }
        if (lane < 4) {
#pragma unroll
            for (int nt = 0; nt < 8; nt++) {
#pragma unroll
                for (int e = 0; e < 2; e++) {
                    const int col = nt * 8 + tg * 2 + e;
                    sumx[wm * 64 + col] = csx[nt * 2 + e];
                    sumy[wm * 64 + col] = csy[nt * 2 + e];
                }
            }
        }
    }
    __syncthreads();
    if (t < 128) {        // 64-row chunk sums: warp-row pairs (0,1) and (2,3)
        const int chunk = t >> 6, col = t & 63;
        const float xs = sumx[(chunk * 2) * 64 + col] + sumx[(chunk * 2 + 1) * 64 + col];
        const float ys = sumy[(chunk * 2) * 64 + col] + sumy[(chunk * 2 + 1) * 64 + col];
        const int cg = chunkbase + chunk;
        const int d = j * 64 + col;
        g_xp[cg * BD + b * DD + d] = xs;
        g_yp[cg * BD + b * DD + d] = ys;
    }
}

// ---------------- all 8 KAN layers: 8 lanes cooperate per (b,d) chain ----------------
__global__ __launch_bounds__(256) void k_mlp_all(const float* __restrict__ mw1, const float* __restrict__ mb1,
                                                 const float* __restrict__ mw2, const float* __restrict__ mb2,
                                                 const float* __restrict__ pw1, const float* __restrict__ pb1,
                                                 const float* __restrict__ pw2, const float* __restrict__ pb2) {
    __shared__ float w[NLAYERS * WSTRIDE];
    const int t = threadIdx.x;
    for (int idx = t; idx < NLAYERS * WSTRIDE; idx += 256) {
        const int l = idx / WSTRIDE;
        const int o = idx - l * WSTRIDE;
        float v = 0.0f;
        if      (o < 32)  v = mw1[l * 32 + o];
        else if (o < 64)  v = mb1[l * 32 + (o - 32)];
        else if (o < 96)  v = mw2[l * 32 + (o - 64)];
        else if (o < 160) v = pw1[l * 64 + (o - 96)];
        else if (o < 192) v = pb1[l * 32 + (o - 160)];
        else if (o < 256) v = pw2[l * 64 + (o - 192)];
        else if (o == 256) v = mb2[l];
        else if (o == 257) v = pb2[2 * l];
        else if (o == 258) v = pb2[2 * l + 1];
        w[idx] = v;
    }
    __syncthreads();

    const int s = t & 7;                       // sublane within 8-lane group
    const int k = blockIdx.x * 32 + (t >> 3);  // (b,d) flat, 32 chains/block

    float xs = g_xp[s * BD + k] + g_xp[(s + 8) * BD + k];
    float ys = g_yp[s * BD + k] + g_yp[(s + 8) * BD + k];
#pragma unroll
    for (int off = 1; off < 8; off <<= 1) {
        xs += __shfl_xor_sync(0xffffffffu, xs, off);
        ys += __shfl_xor_sync(0xffffffffu, ys, off);
    }
    float xm = xs * (1.0f / SS), ym = ys * (1.0f / SS);
    float DX = 0.0f, DY = 0.0f;

    for (int l = 0; l < NLAYERS; l++) {
        const float* wl = w + l * WSTRIDE;
        const float ragg  = sqrtf(xm * xm + ym * ym + EPSF);
        const float thagg = atan2f(ym, xm);
        const float logr = logf(ragg + EPSF);
        float s0, c0;
        sincosf(thagg, &s0, &c0);

        float accp = 0.0f, p0p = 0.0f, p1p = 0.0f;
#pragma unroll
        for (int q = 0; q < 4; q++) {
            const int jj = s * 4 + q;
            const float um = fmaf(logr, wl[jj], wl[32 + jj]);
            accp = fmaf(gelu_exact(um), wl[64 + jj], accp);
            const float up = fmaf(s0, wl[96 + jj], fmaf(c0, wl[128 + jj], wl[160 + jj]));
            const float gp = gelu_exact(up);
            p0p = fmaf(gp, wl[192 + 2 * jj],     p0p);
            p1p = fmaf(gp, wl[192 + 2 * jj + 1], p1p);
        }
#pragma unroll
        for (int off = 1; off < 8; off <<= 1) {
            accp += __shfl_xor_sync(0xffffffffu, accp, off);
            p0p  += __shfl_xor_sync(0xffffffffu, p0p,  off);
            p1p  += __shfl_xor_sync(0xffffffffu, p1p,  off);
        }
        const float rt = expf(accp + wl[256]);
        const float p0 = p0p + wl[257], p1 = p1p + wl[258];
        const float nrm = sqrtf(p0 * p0 + p1 * p1 + EPSF);
        const float tht = atan2f(p0 / nrm, p1 / nrm);
        float sd, cd;
        sincosf(tht, &sd, &cd);
        const float dx = rt * cd, dy = rt * sd;
        xm += dx; ym += dy;
        DX += dx; DY += dy;
    }
    if (s == 0) { g_dx[k] = DX; g_dy[k] = DY; }
}

// ---------------- final pass: r = sqrt((xc0+DX)^2 + (yc0+DY)^2 + eps), chunk sums ----------------
__global__ __launch_bounds__(256) void k_final() {
    __shared__ float sh[4][64][4];
    const int b = blockIdx.y, chunk = blockIdx.x, t = threadIdx.x;
    const int c4 = t & 63, rsub = t >> 6;
    const int dbase = c4 * 4;

    const float4 dxv = *(const float4*)(g_dx + b * DD + dbase);
    const float4 dyv = *(const float4*)(g_dy + b * DD + dbase);

    float s[4] = {0.f, 0.f, 0.f, 0.f};
    const size_t rowbase = (size_t)b * SS + (size_t)chunk * 64;
#pragma unroll 4
    for (int i = 0; i < 16; i++) {
        const size_t idx = (rowbase + rsub + 4 * i) * DD + dbase;
        const __half2* px = (const __half2*)(g_xc + idx);
        const __half2* py = (const __half2*)(g_yc + idx);
        const float2 x01 = __half22float2(px[0]), x23 = __half22float2(px[1]);
        const float2 y01 = __half22float2(py[0]), y23 = __half22float2(py[1]);
        float x0 = x01.x + dxv.x, y0 = y01.x + dyv.x;
        float x1 = x01.y + dxv.y, y1 = y01.y + dyv.y;
        float x2 = x23.x + dxv.z, y2 = y23.x + dyv.z;
        float x3 = x23.y + dxv.w, y3 = y23.y + dyv.w;
        s[0] += sqrtf(fmaf(x0, x0, fmaf(y0, y0, EPSF)));
        s[1] += sqrtf(fmaf(x1, x1, fmaf(y1, y1, EPSF)));
        s[2] += sqrtf(fmaf(x2, x2, fmaf(y2, y2, EPSF)));
        s[3] += sqrtf(fmaf(x3, x3, fmaf(y3, y3, EPSF)));
    }
#pragma unroll
    for (int jj = 0; jj < 4; jj++) sh[rsub][c4][jj] = s[jj];
    __syncthreads();
    if (rsub == 0) {
#pragma unroll
        for (int jj = 0; jj < 4; jj++) {
            float tot = sh[0][c4][jj] + sh[1][c4][jj] + sh[2][c4][jj] + sh[3][c4][jj];
            g_xp[chunk * BD + b * DD + dbase + jj] = tot;
        }
    }
}

// ---------------- classifier (grid-parallel over class groups) ----------------
__global__ __launch_bounds__(256) void k_cls(const float* __restrict__ w1, const float* __restrict__ b1,
                                             const float* __restrict__ w2, const float* __restrict__ b2,
                                             float* __restrict__ out) {
    __shared__ float p[DD];
    __shared__ float hp[8][33];
    __shared__ float h[KANH];
    const int b = blockIdx.x, cg = blockIdx.y, t = threadIdx.x;
    float s = 0.0f;
#pragma unroll
    for (int c = 0; c < NCHUNK; c++) s += g_xp[c * BD + b * DD + t];
    p[t] = s * (1.0f / SS);
    __syncthreads();
    {
        const int jj = t & 31, sl = t >> 5;
        float a = 0.0f;
#pragma unroll
        for (int q = 0; q < 32; q++) {
            const int d2 = sl * 32 + q;
            a = fmaf(p[d2], w1[d2 * KANH + jj], a);
        }
        hp[sl][jj] = a;
    }
    __syncthreads();
    if (t < KANH) {
        float a = b1[t];
#pragma unroll
        for (int s8 = 0; s8 < 8; s8++) a += hp[s8][t];
        h[t] = gelu_exact(a);
    }
    __syncthreads();
    const int c = cg * 250 + t;
    if (t < 250) {
        float a = b2[c];
#pragma unroll
        for (int jj = 0; jj < KANH; jj++) a = fmaf(h[jj], w2[jj * NCLS + c], a);
        out[b * NCLS + c] = a;
    }
}

// ---------------- launch ----------------
extern "C" void kernel_launch(void* const* d_in, const int* in_sizes, int n_in,
                              void* d_out, int out_size) {
    const float* x   = (const float*)d_in[0];
    const float* ew  = (const float*)d_in[1];
    const float* eb  = (const float*)d_in[2];
    const float* mw1 = (const float*)d_in[3];
    const float* mb1 = (const float*)d_in[4];
    const float* mw2 = (const float*)d_in[5];
    const float* mb2 = (const float*)d_in[6];
    const float* pw1 = (const float*)d_in[7];
    const float* pb1 = (const float*)d_in[8];
    const float* pw2 = (const float*)d_in[9];
    const float* pb2 = (const float*)d_in[10];
    const float* cw1 = (const float*)d_in[11];
    const float* cb1 = (const float*)d_in[12];
    const float* cw2 = (const float*)d_in[13];
    const float* cb2 = (const float*)d_in[14];
    float* out = (float*)d_out;

    cudaFuncSetAttribute(k_gemm, cudaFuncAttributeMaxDynamicSharedMemorySize, GSMEM_TOT);

    k_cvt_w<<<512, 256>>>(ew);

    dim3 ggrid(4, 512);                      // x = d-group j (L2 reuse of A across j), y = mtile
    k_gemm<<<ggrid, 256, GSMEM_TOT>>>(x, eb);

    k_mlp_all<<<BD / 32, 256>>>(mw1, mb1, mw2, mb2, pw1, pb1, pw2, pb2);

    dim3 fgrid(NCHUNK, BB);
    k_final<<<fgrid, 256>>>();

    dim3 cgrid(BB, 4);
    k_cls<<<cgrid, 256>>>(cw1, cb1, cw2, cb2, out);
}

// round 16
// speedup vs baseline: 2.1853x; 1.1869x over previous
#include <cuda_runtime.h>
#include <cuda_bf16.h>
#include <cuda_fp16.h>
#include <math.h>
#include <stdint.h>

#define BB 64
#define SS 1024
#define DD 256
#define NLAYERS 8
#define KANH 32
#define NCLS 1000
#define EPSF 1e-8f
#define PI_F 3.14159265358979323846f
#define NCHUNK 16
#define BD (BB*DD)
#define WSTRIDE 260

// ---------------- persistent device scratch ----------------
__device__ __half g_xc[BB*SS*DD];          // xc0 (fp16 — only feeds final pooled mean)
__device__ __half g_yc[BB*SS*DD];
__device__ float g_xp[NCHUNK*BD];          // fp32 chunk sums (feed the sensitive KAN chain)
__device__ float g_yp[NCHUNK*BD];
__device__ float g_dx[BD];
__device__ float g_dy[BD];
__device__ __nv_bfloat16 g_bhT[512*256];   // W hi, transposed [n][k]
__device__ __nv_bfloat16 g_blT[512*256];   // W lo, transposed [n][k]

__device__ __forceinline__ float gelu_exact(float v) {
    return 0.5f * v * (1.0f + erff(v * 0.70710678118654752440f));
}
__device__ __forceinline__ uint32_t smem_u32(const void* p) {
    uint32_t a;
    asm("{ .reg .u64 t; cvta.to.shared.u64 t, %1; cvt.u32.u64 %0, t; }" : "=r"(a) : "l"(p));
    return a;
}
__device__ __forceinline__ void mma16816(float c[4], const uint32_t a[4], const uint32_t b[2]) {
    asm volatile("mma.sync.aligned.m16n8k16.row.col.f32.bf16.bf16.f32 "
                 "{%0,%1,%2,%3}, {%4,%5,%6,%7}, {%8,%9}, {%0,%1,%2,%3};"
                 : "+f"(c[0]), "+f"(c[1]), "+f"(c[2]), "+f"(c[3])
                 : "r"(a[0]), "r"(a[1]), "r"(a[2]), "r"(a[3]), "r"(b[0]), "r"(b[1]));
}
__device__ __forceinline__ void ldm_x4(uint32_t r[4], uint32_t addr) {
    asm volatile("ldmatrix.sync.aligned.m8n8.x4.shared.b16 {%0,%1,%2,%3}, [%4];"
                 : "=r"(r[0]), "=r"(r[1]), "=r"(r[2]), "=r"(r[3]) : "r"(addr));
}

// ---------------- W split conversion (A converts inline in k_gemm) ----------------
__global__ __launch_bounds__(256) void k_cvt_w(const float* __restrict__ W) {
    const int idx = blockIdx.x * 256 + threadIdx.x;   // [n][k], 512*256
    const int n = idx >> 8, k = idx & 255;
    const float v = W[k * 512 + n];
    __nv_bfloat16 h = __float2bfloat16(v);
    g_bhT[idx] = h;
    g_blT[idx] = __float2bfloat16(v - __bfloat162float(h));
}

// ---------------- mma.sync embed GEMM + fused polar epilogue ----------------
// Block: 128 rows x 128 cols (64 h1-cols + 64 h2-cols of d-group j).
// 8 warps: wm = w&3 -> 32-row slice; half = w>>2 -> h1 (0) or h2 (1).
// K=256 in 32-chunks, 2-stage double buffer: B via cp.async, A via reg-prefetch
// LDG fp32 + inline hi/lo bf16 conversion. 3-pass split-bf16 (hh + lh + hl),
// all smem operand feeding via ldmatrix.x4 (conflict-free at 80B row stride).

#define A_STRIDE 40                       // bf16 per smem row (32 + 8 pad) = 80 bytes
#define ARR_BYTES (128*A_STRIDE*2)        // 10240 per array
#define STAGE_BYTES (4*ARR_BYTES)         // Ah,Al,Bh,Bl = 40960
#define GSMEM_TOT (2*STAGE_BYTES)         // 81920 (>= epilogue stage 33280)
#define STG_STRIDE 65

__device__ __forceinline__ void fill_B(uint32_t sbase, char* smem, int t, int j, int s, int kc) {
    const uint32_t base = sbase + (uint32_t)s * STAGE_BYTES + 2u * ARR_BYTES;
#pragma unroll
    for (int it = 0; it < 4; it++) {
        const int c = it * 256 + t;            // 0..1023
        const int arr = c >> 9, rem = c & 511;
        const int row = rem >> 2, seg = rem & 3;
        const int nglob = (row < 64) ? (j * 64 + row) : (256 + j * 64 + (row - 64));
        const __nv_bfloat16* src = ((arr == 0) ? g_bhT : g_blT) + nglob * 256 + kc * 32 + seg * 8;
        const uint32_t dst = base + (uint32_t)arr * ARR_BYTES + (uint32_t)row * 80 + (uint32_t)seg * 16;
        asm volatile("cp.async.cg.shared.global [%0], [%1], 16;" :: "r"(dst), "l"(src) : "memory");
    }
    asm volatile("cp.async.commit_group;" ::: "memory");
}

struct AReg { float4 v[4]; };

__device__ __forceinline__ void load_A(AReg& r, const float* __restrict__ A, int bm, int t, int kc) {
    const int row = t >> 1, ch = t & 1;
    const float* p = A + (size_t)(bm + row) * 256 + kc * 32 + ch * 16;
    r.v[0] = *(const float4*)(p);
    r.v[1] = *(const float4*)(p + 4);
    r.v[2] = *(const float4*)(p + 8);
    r.v[3] = *(const float4*)(p + 12);
}

__device__ __forceinline__ void store_A(const AReg& r, char* smem, int t, int s) {
    const int row = t >> 1, ch = t & 1;
    const float* f = (const float*)&r;
    uint32_t ah[8], al[8];
#pragma unroll
    for (int q = 0; q < 8; q++) {
        const float a0 = f[2 * q], a1 = f[2 * q + 1];
        __nv_bfloat16 h0 = __float2bfloat16(a0), h1 = __float2bfloat16(a1);
        __nv_bfloat16 l0 = __float2bfloat16(a0 - __bfloat162float(h0));
        __nv_bfloat16 l1 = __float2bfloat16(a1 - __bfloat162float(h1));
        ah[q] = (uint32_t)__bfloat16_as_ushort(h0) | ((uint32_t)__bfloat16_as_ushort(h1) << 16);
        al[q] = (uint32_t)__bfloat16_as_ushort(l0) | ((uint32_t)__bfloat16_as_ushort(l1) << 16);
    }
    char* base = smem + (size_t)s * STAGE_BYTES;
    const uint32_t off = (uint32_t)row * 80 + (uint32_t)ch * 32;
    *(uint4*)(base + off)                   = make_uint4(ah[0], ah[1], ah[2], ah[3]);
    *(uint4*)(base + off + 16)              = make_uint4(ah[4], ah[5], ah[6], ah[7]);
    *(uint4*)(base + ARR_BYTES + off)       = make_uint4(al[0], al[1], al[2], al[3]);
    *(uint4*)(base + ARR_BYTES + off + 16)  = make_uint4(al[4], al[5], al[6], al[7]);
}

__global__ __launch_bounds__(256, 2) void k_gemm(const float* __restrict__ A,
                                                 const float* __restrict__ bias) {
    extern __shared__ char smem[];
    const uint32_t sbase = smem_u32(smem);
    const int t = threadIdx.x;
    const int lane = t & 31, w = t >> 5;
    const int g = lane >> 2, tg = lane & 3;
    const int wm = w & 3, half = w >> 2;
    const int j = blockIdx.x, mtile = blockIdx.y;
    const int bm = mtile * 128;
    const int b = bm >> 10;
    const int chunkbase = (bm & 1023) >> 6;

    __shared__ float sumx[256], sumy[256];
    __shared__ float sb1[64], sb2[64];
    if (t < 64) { sb1[t] = bias[j * 64 + t]; sb2[t] = bias[256 + j * 64 + t]; }

    // ldmatrix per-lane address components (within a stage/array)
    // A tile (m16k16 -> x4): lanes 0-7 rows0-7 k0 | 8-15 rows8-15 k0 | 16-23 rows0-7 k+8 | 24-31 rows8-15 k+8
    const uint32_t aoffL = (uint32_t)(wm * 32 + (lane & 15)) * 80 + ((uint32_t)(lane >> 4) << 4);
    // B tiles (2 x n8k16 -> x4): lanes 0-7 n0-7 k0 | 8-15 n0-7 k+8 | 16-23 n8-15 k0 | 24-31 n8-15 k+8
    const uint32_t boffL = (uint32_t)(half * 64 + (lane & 7) + ((lane >> 4) << 3)) * 80
                         + (((uint32_t)(lane >> 3) & 1u) << 4);

    float acc[2][8][4];
#pragma unroll
    for (int mt = 0; mt < 2; mt++)
#pragma unroll
        for (int nt = 0; nt < 8; nt++)
#pragma unroll
            for (int c = 0; c < 4; c++) acc[mt][nt][c] = 0.0f;

    AReg areg;
    fill_B(sbase, smem, t, j, 0, 0);
    load_A(areg, A, bm, t, 0);
    store_A(areg, smem, t, 0);
    asm volatile("cp.async.wait_group 0;" ::: "memory");
    __syncthreads();

    for (int kc = 0; kc < 8; kc++) {
        const int cur = kc & 1;
        if (kc < 7) {
            fill_B(sbase, smem, t, j, cur ^ 1, kc + 1);
            load_A(areg, A, bm, t, kc + 1);
        }

        const uint32_t stg = sbase + (uint32_t)cur * STAGE_BYTES;

#pragma unroll
        for (int kk = 0; kk < 2; kk++) {
            const uint32_t kb = (uint32_t)kk * 32;
            uint32_t ah[2][4], al[2][4];
#pragma unroll
            for (int mt = 0; mt < 2; mt++) {
                const uint32_t ao = stg + aoffL + (uint32_t)(mt * 16) * 80 + kb;
                ldm_x4(ah[mt], ao);
                ldm_x4(al[mt], ao + ARR_BYTES);
            }
#pragma unroll
            for (int ntp = 0; ntp < 4; ntp++) {
                const uint32_t bo = stg + 2u * ARR_BYTES + boffL + (uint32_t)(ntp * 16) * 80 + kb;
                uint32_t bh[4], bl[4];
                ldm_x4(bh, bo);
                ldm_x4(bl, bo + ARR_BYTES);
                const int n0 = ntp * 2, n1 = ntp * 2 + 1;
                mma16816(acc[0][n0], ah[0], bh);
                mma16816(acc[1][n0], ah[1], bh);
                mma16816(acc[0][n1], ah[0], bh + 2);
                mma16816(acc[1][n1], ah[1], bh + 2);
                mma16816(acc[0][n0], al[0], bh);
                mma16816(acc[1][n0], al[1], bh);
                mma16816(acc[0][n1], al[0], bh + 2);
                mma16816(acc[1][n1], al[1], bh + 2);
                mma16816(acc[0][n0], ah[0], bl);
                mma16816(acc[1][n0], ah[1], bl);
                mma16816(acc[0][n1], ah[0], bl + 2);
                mma16816(acc[1][n1], ah[1], bl + 2);
            }
        }

        if (kc < 7) {
            store_A(areg, smem, t, cur ^ 1);
            asm volatile("cp.async.wait_group 0;" ::: "memory");
        }
        __syncthreads();
    }

    // -------- epilogue: h2 staged through smem, polar, fp16 writes, chunk sums --------
    float* stage = (float*)smem;   // 128 x STG_STRIDE floats (overlays mainloop smem)
    if (half == 1) {
#pragma unroll
        for (int mt = 0; mt < 2; mt++)
#pragma unroll
            for (int nt = 0; nt < 8; nt++) {
                const int r0 = wm * 32 + mt * 16 + g;
                const int col = nt * 8 + tg * 2;
                stage[r0 * STG_STRIDE + col]           = acc[mt][nt][0] + sb2[col];
                stage[r0 * STG_STRIDE + col + 1]       = acc[mt][nt][1] + sb2[col + 1];
                stage[(r0 + 8) * STG_STRIDE + col]     = acc[mt][nt][2] + sb2[col];
                stage[(r0 + 8) * STG_STRIDE + col + 1] = acc[mt][nt][3] + sb2[col + 1];
            }
    }
    __syncthreads();
    if (half == 0) {
        float csx[16], csy[16];
#pragma unroll
        for (int q = 0; q < 16; q++) { csx[q] = 0.0f; csy[q] = 0.0f; }
#pragma unroll
        for (int mt = 0; mt < 2; mt++)
#pragma unroll
            for (int nt = 0; nt < 8; nt++) {
                const int col = nt * 8 + tg * 2;
                const int d = j * 64 + col;
                const float b0 = sb1[col], b1v = sb1[col + 1];
#pragma unroll
                for (int rh = 0; rh < 2; rh++) {
                    const int row = wm * 32 + mt * 16 + g + rh * 8;
                    const float h1a = acc[mt][nt][rh * 2 + 0] + b0;
                    const float h1b = acc[mt][nt][rh * 2 + 1] + b1v;
                    const float h2a = stage[row * STG_STRIDE + col];
                    const float h2b = stage[row * STG_STRIDE + col + 1];
                    const float ra = fabsf(h1a) + 0.1f;
                    const float rb = fabsf(h1b) + 0.1f;
                    float sa, ca, sb_, cb;
                    sincosf(PI_F * h2a, &sa, &ca);
                    sincosf(PI_F * h2b, &sb_, &cb);
                    const float xa = ra * ca, ya = ra * sa;
                    const float xb = rb * cb, yb = rb * sb_;
                    *(__half2*)(g_xc + (size_t)(bm + row) * 256 + d) = __floats2half2_rn(xa, xb);
                    *(__half2*)(g_yc + (size_t)(bm + row) * 256 + d) = __floats2half2_rn(ya, yb);
                    csx[nt * 2]     += xa;  csx[nt * 2 + 1] += xb;
                    csy[nt * 2]     += ya;  csy[nt * 2 + 1] += yb;
                }
            }
#pragma unroll
        for (int off = 4; off <= 16; off <<= 1)
#pragma unroll
            for (int q = 0; q < 16; q++) {
                csx[q] += __shfl_xor_sync(0xffffffffu, csx[q], off);
                csy[q] += __shfl_xor_sync(0xffffffffu, csy[q], off);
            }
        if (lane < 4) {
#pragma unroll
            for (int nt = 0; nt < 8; nt++) {
#pragma unroll
                for (int e = 0; e < 2; e++) {
                    const int col = nt * 8 + tg * 2 + e;
                    sumx[wm * 64 + col] = csx[nt * 2 + e];
                    sumy[wm * 64 + col] = csy[nt * 2 + e];
                }
            }
        }
    }
    __syncthreads();
    if (t < 128) {        // 64-row chunk sums: warp-row pairs (0,1) and (2,3)
        const int chunk = t >> 6, col = t & 63;
        const float xs = sumx[(chunk * 2) * 64 + col] + sumx[(chunk * 2 + 1) * 64 + col];
        const float ys = sumy[(chunk * 2) * 64 + col] + sumy[(chunk * 2 + 1) * 64 + col];
        const int cg = chunkbase + chunk;
        const int d = j * 64 + col;
        g_xp[cg * BD + b * DD + d] = xs;
        g_yp[cg * BD + b * DD + d] = ys;
    }
}

// ---------------- all 8 KAN layers: 8 lanes cooperate per (b,d) chain ----------------
__global__ __launch_bounds__(256) void k_mlp_all(const float* __restrict__ mw1, const float* __restrict__ mb1,
                                                 const float* __restrict__ mw2, const float* __restrict__ mb2,
                                                 const float* __restrict__ pw1, const float* __restrict__ pb1,
                                                 const float* __restrict__ pw2, const float* __restrict__ pb2) {
    __shared__ float w[NLAYERS * WSTRIDE];
    const int t = threadIdx.x;
    for (int idx = t; idx < NLAYERS * WSTRIDE; idx += 256) {
        const int l = idx / WSTRIDE;
        const int o = idx - l * WSTRIDE;
        float v = 0.0f;
        if      (o < 32)  v = mw1[l * 32 + o];
        else if (o < 64)  v = mb1[l * 32 + (o - 32)];
        else if (o < 96)  v = mw2[l * 32 + (o - 64)];
        else if (o < 160) v = pw1[l * 64 + (o - 96)];
        else if (o < 192) v = pb1[l * 32 + (o - 160)];
        else if (o < 256) v = pw2[l * 64 + (o - 192)];
        else if (o == 256) v = mb2[l];
        else if (o == 257) v = pb2[2 * l];
        else if (o == 258) v = pb2[2 * l + 1];
        w[idx] = v;
    }
    __syncthreads();

    const int s = t & 7;                       // sublane within 8-lane group
    const int k = blockIdx.x * 32 + (t >> 3);  // (b,d) flat, 32 chains/block

    float xs = g_xp[s * BD + k] + g_xp[(s + 8) * BD + k];
    float ys = g_yp[s * BD + k] + g_yp[(s + 8) * BD + k];
#pragma unroll
    for (int off = 1; off < 8; off <<= 1) {
        xs += __shfl_xor_sync(0xffffffffu, xs, off);
        ys += __shfl_xor_sync(0xffffffffu, ys, off);
    }
    float xm = xs * (1.0f / SS), ym = ys * (1.0f / SS);
    float DX = 0.0f, DY = 0.0f;

    for (int l = 0; l < NLAYERS; l++) {
        const float* wl = w + l * WSTRIDE;
        const float ragg  = sqrtf(xm * xm + ym * ym + EPSF);
        const float thagg = atan2f(ym, xm);
        const float logr = logf(ragg + EPSF);
        float s0, c0;
        sincosf(thagg, &s0, &c0);

        float accp = 0.0f, p0p = 0.0f, p1p = 0.0f;
#pragma unroll
        for (int q = 0; q < 4; q++) {
            const int jj = s * 4 + q;
            const float um = fmaf(logr, wl[jj], wl[32 + jj]);
            accp = fmaf(gelu_exact(um), wl[64 + jj], accp);
            const float up = fmaf(s0, wl[96 + jj], fmaf(c0, wl[128 + jj], wl[160 + jj]));
            const float gp = gelu_exact(up);
            p0p = fmaf(gp, wl[192 + 2 * jj],     p0p);
            p1p = fmaf(gp, wl[192 + 2 * jj + 1], p1p);
        }
#pragma unroll
        for (int off = 1; off < 8; off <<= 1) {
            accp += __shfl_xor_sync(0xffffffffu, accp, off);
            p0p  += __shfl_xor_sync(0xffffffffu, p0p,  off);
            p1p  += __shfl_xor_sync(0xffffffffu, p1p,  off);
        }
        const float rt = expf(accp + wl[256]);
        const float p0 = p0p + wl[257], p1 = p1p + wl[258];
        const float nrm = sqrtf(p0 * p0 + p1 * p1 + EPSF);
        const float tht = atan2f(p0 / nrm, p1 / nrm);
        float sd, cd;
        sincosf(tht, &sd, &cd);
        const float dx = rt * cd, dy = rt * sd;
        xm += dx; ym += dy;
        DX += dx; DY += dy;
    }
    if (s == 0) { g_dx[k] = DX; g_dy[k] = DY; }
}

// ---------------- final pass: r = sqrt((xc0+DX)^2 + (yc0+DY)^2 + eps), chunk sums ----------------
__global__ __launch_bounds__(256) void k_final() {
    __shared__ float sh[4][64][4];
    const int b = blockIdx.y, chunk = blockIdx.x, t = threadIdx.x;
    const int c4 = t & 63, rsub = t >> 6;
    const int dbase = c4 * 4;

    const float4 dxv = *(const float4*)(g_dx + b * DD + dbase);
    const float4 dyv = *(const float4*)(g_dy + b * DD + dbase);

    float s[4] = {0.f, 0.f, 0.f, 0.f};
    const size_t rowbase = (size_t)b * SS + (size_t)chunk * 64;
#pragma unroll 4
    for (int i = 0; i < 16; i++) {
        const size_t idx = (rowbase + rsub + 4 * i) * DD + dbase;
        const __half2* px = (const __half2*)(g_xc + idx);
        const __half2* py = (const __half2*)(g_yc + idx);
        const float2 x01 = __half22float2(px[0]), x23 = __half22float2(px[1]);
        const float2 y01 = __half22float2(py[0]), y23 = __half22float2(py[1]);
        float x0 = x01.x + dxv.x, y0 = y01.x + dyv.x;
        float x1 = x01.y + dxv.y, y1 = y01.y + dyv.y;
        float x2 = x23.x + dxv.z, y2 = y23.x + dyv.z;
        float x3 = x23.y + dxv.w, y3 = y23.y + dyv.w;
        s[0] += sqrtf(fmaf(x0, x0, fmaf(y0, y0, EPSF)));
        s[1] += sqrtf(fmaf(x1, x1, fmaf(y1, y1, EPSF)));
        s[2] += sqrtf(fmaf(x2, x2, fmaf(y2, y2, EPSF)));
        s[3] += sqrtf(fmaf(x3, x3, fmaf(y3, y3, EPSF)));
    }
#pragma unroll
    for (int jj = 0; jj < 4; jj++) sh[rsub][c4][jj] = s[jj];
    __syncthreads();
    if (rsub == 0) {
#pragma unroll
        for (int jj = 0; jj < 4; jj++) {
            float tot = sh[0][c4][jj] + sh[1][c4][jj] + sh[2][c4][jj] + sh[3][c4][jj];
            g_xp[chunk * BD + b * DD + dbase + jj] = tot;
        }
    }
}

// ---------------- classifier (grid-parallel over class groups) ----------------
__global__ __launch_bounds__(256) void k_cls(const float* __restrict__ w1, const float* __restrict__ b1,
                                             const float* __restrict__ w2, const float* __restrict__ b2,
                                             float* __restrict__ out) {
    __shared__ float p[DD];
    __shared__ float hp[8][33];
    __shared__ float h[KANH];
    const int b = blockIdx.x, cg = blockIdx.y, t = threadIdx.x;
    float s = 0.0f;
#pragma unroll
    for (int c = 0; c < NCHUNK; c++) s += g_xp[c * BD + b * DD + t];
    p[t] = s * (1.0f / SS);
    __syncthreads();
    {
        const int jj = t & 31, sl = t >> 5;
        float a = 0.0f;
#pragma unroll
        for (int q = 0; q < 32; q++) {
            const int d2 = sl * 32 + q;
            a = fmaf(p[d2], w1[d2 * KANH + jj], a);
        }
        hp[sl][jj] = a;
    }
    __syncthreads();
    if (t < KANH) {
        float a = b1[t];
#pragma unroll
        for (int s8 = 0; s8 < 8; s8++) a += hp[s8][t];
        h[t] = gelu_exact(a);
    }
    __syncthreads();
    const int c = cg * 250 + t;
    if (t < 250) {
        float a = b2[c];
#pragma unroll
        for (int jj = 0; jj < KANH; jj++) a = fmaf(h[jj], w2[jj * NCLS + c], a);
        out[b * NCLS + c] = a;
    }
}

// ---------------- launch ----------------
extern "C" void kernel_launch(void* const* d_in, const int* in_sizes, int n_in,
                              void* d_out, int out_size) {
    const float* x   = (const float*)d_in[0];
    const float* ew  = (const float*)d_in[1];
    const float* eb  = (const float*)d_in[2];
    const float* mw1 = (const float*)d_in[3];
    const float* mb1 = (const float*)d_in[4];
    const float* mw2 = (const float*)d_in[5];
    const float* mb2 = (const float*)d_in[6];
    const float* pw1 = (const float*)d_in[7];
    const float* pb1 = (const float*)d_in[8];
    const float* pw2 = (const float*)d_in[9];
    const float* pb2 = (const float*)d_in[10];
    const float* cw1 = (const float*)d_in[11];
    const float* cb1 = (const float*)d_in[12];
    const float* cw2 = (const float*)d_in[13];
    const float* cb2 = (const float*)d_in[14];
    float* out = (float*)d_out;

    cudaFuncSetAttribute(k_gemm, cudaFuncAttributeMaxDynamicSharedMemorySize, GSMEM_TOT);

    k_cvt_w<<<512, 256>>>(ew);

    dim3 ggrid(4, 512);                      // x = d-group j (L2 reuse of A across j), y = mtile
    k_gemm<<<ggrid, 256, GSMEM_TOT>>>(x, eb);

    k_mlp_all<<<BD / 32, 256>>>(mw1, mb1, mw2, mb2, pw1, pb1, pw2, pb2);

    dim3 fgrid(NCHUNK, BB);
    k_final<<<fgrid, 256>>>();

    dim3 cgrid(BB, 4);
    k_cls<<<cgrid, 256>>>(cw1, cb1, cw2, cb2, out);
}

// round 17
// speedup vs baseline: 2.4830x; 1.1362x over previous
#include <cuda_runtime.h>
#include <cuda_bf16.h>
#include <cuda_fp16.h>
#include <math.h>
#include <stdint.h>

#define BB 64
#define SS 1024
#define DD 256
#define NLAYERS 8
#define KANH 32
#define NCLS 1000
#define EPSF 1e-8f
#define PI_F 3.14159265358979323846f
#define NCHUNK 16
#define BD (BB*DD)
#define WSTRIDE 260

// ---------------- persistent device scratch ----------------
__device__ __half g_xc[BB*SS*DD];          // xc0 (fp16 — only feeds final pooled mean)
__device__ __half g_yc[BB*SS*DD];
__device__ float g_xp[NCHUNK*BD];          // fp32 chunk sums (feed the sensitive KAN chain)
__device__ float g_yp[NCHUNK*BD];
__device__ float g_dx[BD];
__device__ float g_dy[BD];
__device__ __nv_bfloat16 g_bhT[512*256];   // W hi, transposed [n][k]
__device__ __nv_bfloat16 g_blT[512*256];   // W lo, transposed [n][k]

__device__ __forceinline__ float gelu_exact(float v) {
    return 0.5f * v * (1.0f + erff(v * 0.70710678118654752440f));
}
__device__ __forceinline__ uint32_t smem_u32(const void* p) {
    uint32_t a;
    asm("{ .reg .u64 t; cvta.to.shared.u64 t, %1; cvt.u32.u64 %0, t; }" : "=r"(a) : "l"(p));
    return a;
}
__device__ __forceinline__ void mma16816(float c[4], const uint32_t a[4], const uint32_t b[2]) {
    asm volatile("mma.sync.aligned.m16n8k16.row.col.f32.bf16.bf16.f32 "
                 "{%0,%1,%2,%3}, {%4,%5,%6,%7}, {%8,%9}, {%0,%1,%2,%3};"
                 : "+f"(c[0]), "+f"(c[1]), "+f"(c[2]), "+f"(c[3])
                 : "r"(a[0]), "r"(a[1]), "r"(a[2]), "r"(a[3]), "r"(b[0]), "r"(b[1]));
}
__device__ __forceinline__ void ldm_x4(uint32_t r[4], uint32_t addr) {
    asm volatile("ldmatrix.sync.aligned.m8n8.x4.shared.b16 {%0,%1,%2,%3}, [%4];"
                 : "=r"(r[0]), "=r"(r[1]), "=r"(r[2]), "=r"(r[3]) : "r"(addr));
}

// ---------------- W split conversion (A converts inline in k_gemm) ----------------
__global__ __launch_bounds__(256) void k_cvt_w(const float* __restrict__ W) {
    const int idx = blockIdx.x * 256 + threadIdx.x;   // [n][k], 512*256
    const int n = idx >> 8, k = idx & 255;
    const float v = W[k * 512 + n];
    __nv_bfloat16 h = __float2bfloat16(v);
    g_bhT[idx] = h;
    g_blT[idx] = __float2bfloat16(v - __bfloat162float(h));
}

// ---------------- mma.sync embed GEMM + fused polar epilogue ----------------
// Block: 128 rows x 128 cols (64 h1-cols + 64 h2-cols of d-group j).
// 8 warps: wm = w&3 -> 32-row slice; half = w>>2 -> h1 (0) or h2 (1).
// K=256 in 32-chunks, 2-stage double buffer: B via cp.async, A via reg-prefetch
// LDG fp32 + inline hi/lo bf16 conversion. 3-pass split-bf16 (hh + lh + hl),
// smem operand feeding via ldmatrix.x4; MUFU __sincosf in the polar epilogue.

#define A_STRIDE 40                       // bf16 per smem row (32 + 8 pad) = 80 bytes
#define ARR_BYTES (128*A_STRIDE*2)        // 10240 per array
#define STAGE_BYTES (4*ARR_BYTES)         // Ah,Al,Bh,Bl = 40960
#define GSMEM_TOT (2*STAGE_BYTES)         // 81920 (>= epilogue stage 33280)
#define STG_STRIDE 65

__device__ __forceinline__ void fill_B(uint32_t sbase, char* smem, int t, int j, int s, int kc) {
    const uint32_t base = sbase + (uint32_t)s * STAGE_BYTES + 2u * ARR_BYTES;
#pragma unroll
    for (int it = 0; it < 4; it++) {
        const int c = it * 256 + t;            // 0..1023
        const int arr = c >> 9, rem = c & 511;
        const int row = rem >> 2, seg = rem & 3;
        const int nglob = (row < 64) ? (j * 64 + row) : (256 + j * 64 + (row - 64));
        const __nv_bfloat16* src = ((arr == 0) ? g_bhT : g_blT) + nglob * 256 + kc * 32 + seg * 8;
        const uint32_t dst = base + (uint32_t)arr * ARR_BYTES + (uint32_t)row * 80 + (uint32_t)seg * 16;
        asm volatile("cp.async.cg.shared.global [%0], [%1], 16;" :: "r"(dst), "l"(src) : "memory");
    }
    asm volatile("cp.async.commit_group;" ::: "memory");
}

struct AReg { float4 v[4]; };

__device__ __forceinline__ void load_A(AReg& r, const float* __restrict__ A, int bm, int t, int kc) {
    const int row = t >> 1, ch = t & 1;
    const float* p = A + (size_t)(bm + row) * 256 + kc * 32 + ch * 16;
    r.v[0] = *(const float4*)(p);
    r.v[1] = *(const float4*)(p + 4);
    r.v[2] = *(const float4*)(p + 8);
    r.v[3] = *(const float4*)(p + 12);
}

__device__ __forceinline__ void store_A(const AReg& r, char* smem, int t, int s) {
    const int row = t >> 1, ch = t & 1;
    const float* f = (const float*)&r;
    uint32_t ah[8], al[8];
#pragma unroll
    for (int q = 0; q < 8; q++) {
        const float a0 = f[2 * q], a1 = f[2 * q + 1];
        __nv_bfloat16 h0 = __float2bfloat16(a0), h1 = __float2bfloat16(a1);
        __nv_bfloat16 l0 = __float2bfloat16(a0 - __bfloat162float(h0));
        __nv_bfloat16 l1 = __float2bfloat16(a1 - __bfloat162float(h1));
        ah[q] = (uint32_t)__bfloat16_as_ushort(h0) | ((uint32_t)__bfloat16_as_ushort(h1) << 16);
        al[q] = (uint32_t)__bfloat16_as_ushort(l0) | ((uint32_t)__bfloat16_as_ushort(l1) << 16);
    }
    char* base = smem + (size_t)s * STAGE_BYTES;
    const uint32_t off = (uint32_t)row * 80 + (uint32_t)ch * 32;
    *(uint4*)(base + off)                   = make_uint4(ah[0], ah[1], ah[2], ah[3]);
    *(uint4*)(base + off + 16)              = make_uint4(ah[4], ah[5], ah[6], ah[7]);
    *(uint4*)(base + ARR_BYTES + off)       = make_uint4(al[0], al[1], al[2], al[3]);
    *(uint4*)(base + ARR_BYTES + off + 16)  = make_uint4(al[4], al[5], al[6], al[7]);
}

__global__ __launch_bounds__(256, 2) void k_gemm(const float* __restrict__ A,
                                                 const float* __restrict__ bias) {
    extern __shared__ char smem[];
    const uint32_t sbase = smem_u32(smem);
    const int t = threadIdx.x;
    const int lane = t & 31, w = t >> 5;
    const int g = lane >> 2, tg = lane & 3;
    const int wm = w & 3, half = w >> 2;
    const int j = blockIdx.x, mtile = blockIdx.y;
    const int bm = mtile * 128;
    const int b = bm >> 10;
    const int chunkbase = (bm & 1023) >> 6;

    __shared__ float sumx[256], sumy[256];
    __shared__ float sb1[64], sb2[64];
    if (t < 64) { sb1[t] = bias[j * 64 + t]; sb2[t] = bias[256 + j * 64 + t]; }

    // ldmatrix per-lane address components (within a stage/array)
    const uint32_t aoffL = (uint32_t)(wm * 32 + (lane & 15)) * 80 + ((uint32_t)(lane >> 4) << 4);
    const uint32_t boffL = (uint32_t)(half * 64 + (lane & 7) + ((lane >> 4) << 3)) * 80
                         + (((uint32_t)(lane >> 3) & 1u) << 4);

    float acc[2][8][4];
#pragma unroll
    for (int mt = 0; mt < 2; mt++)
#pragma unroll
        for (int nt = 0; nt < 8; nt++)
#pragma unroll
            for (int c = 0; c < 4; c++) acc[mt][nt][c] = 0.0f;

    AReg areg;
    fill_B(sbase, smem, t, j, 0, 0);
    load_A(areg, A, bm, t, 0);
    store_A(areg, smem, t, 0);
    asm volatile("cp.async.wait_group 0;" ::: "memory");
    __syncthreads();

    for (int kc = 0; kc < 8; kc++) {
        const int cur = kc & 1;
        if (kc < 7) {
            fill_B(sbase, smem, t, j, cur ^ 1, kc + 1);
            load_A(areg, A, bm, t, kc + 1);
        }

        const uint32_t stg = sbase + (uint32_t)cur * STAGE_BYTES;

#pragma unroll
        for (int kk = 0; kk < 2; kk++) {
            const uint32_t kb = (uint32_t)kk * 32;
            uint32_t ah[2][4], al[2][4];
#pragma unroll
            for (int mt = 0; mt < 2; mt++) {
                const uint32_t ao = stg + aoffL + (uint32_t)(mt * 16) * 80 + kb;
                ldm_x4(ah[mt], ao);
                ldm_x4(al[mt], ao + ARR_BYTES);
            }
#pragma unroll
            for (int ntp = 0; ntp < 4; ntp++) {
                const uint32_t bo = stg + 2u * ARR_BYTES + boffL + (uint32_t)(ntp * 16) * 80 + kb;
                uint32_t bh[4], bl[4];
                ldm_x4(bh, bo);
                ldm_x4(bl, bo + ARR_BYTES);
                const int n0 = ntp * 2, n1 = ntp * 2 + 1;
                mma16816(acc[0][n0], ah[0], bh);
                mma16816(acc[1][n0], ah[1], bh);
                mma16816(acc[0][n1], ah[0], bh + 2);
                mma16816(acc[1][n1], ah[1], bh + 2);
                mma16816(acc[0][n0], al[0], bh);
                mma16816(acc[1][n0], al[1], bh);
                mma16816(acc[0][n1], al[0], bh + 2);
                mma16816(acc[1][n1], al[1], bh + 2);
                mma16816(acc[0][n0], ah[0], bl);
                mma16816(acc[1][n0], ah[1], bl);
                mma16816(acc[0][n1], ah[0], bl + 2);
                mma16816(acc[1][n1], ah[1], bl + 2);
            }
        }

        if (kc < 7) {
            store_A(areg, smem, t, cur ^ 1);
            asm volatile("cp.async.wait_group 0;" ::: "memory");
        }
        __syncthreads();
    }

    // -------- epilogue: h2 staged through smem, polar (MUFU sincos), fp16 writes, chunk sums --------
    float* stage = (float*)smem;   // 128 x STG_STRIDE floats (overlays mainloop smem)
    if (half == 1) {
#pragma unroll
        for (int mt = 0; mt < 2; mt++)
#pragma unroll
            for (int nt = 0; nt < 8; nt++) {
                const int r0 = wm * 32 + mt * 16 + g;
                const int col = nt * 8 + tg * 2;
                stage[r0 * STG_STRIDE + col]           = acc[mt][nt][0] + sb2[col];
                stage[r0 * STG_STRIDE + col + 1]       = acc[mt][nt][1] + sb2[col + 1];
                stage[(r0 + 8) * STG_STRIDE + col]     = acc[mt][nt][2] + sb2[col];
                stage[(r0 + 8) * STG_STRIDE + col + 1] = acc[mt][nt][3] + sb2[col + 1];
            }
    }
    __syncthreads();
    if (half == 0) {
        float csx[16], csy[16];
#pragma unroll
        for (int q = 0; q < 16; q++) { csx[q] = 0.0f; csy[q] = 0.0f; }
#pragma unroll
        for (int mt = 0; mt < 2; mt++)
#pragma unroll
            for (int nt = 0; nt < 8; nt++) {
                const int col = nt * 8 + tg * 2;
                const int d = j * 64 + col;
                const float b0 = sb1[col], b1v = sb1[col + 1];
#pragma unroll
                for (int rh = 0; rh < 2; rh++) {
                    const int row = wm * 32 + mt * 16 + g + rh * 8;
                    const float h1a = acc[mt][nt][rh * 2 + 0] + b0;
                    const float h1b = acc[mt][nt][rh * 2 + 1] + b1v;
                    const float h2a = stage[row * STG_STRIDE + col];
                    const float h2b = stage[row * STG_STRIDE + col + 1];
                    const float ra = fabsf(h1a) + 0.1f;
                    const float rb = fabsf(h1b) + 0.1f;
                    float sa, ca, sb_, cb;
                    __sincosf(PI_F * h2a, &sa, &ca);
                    __sincosf(PI_F * h2b, &sb_, &cb);
                    const float xa = ra * ca, ya = ra * sa;
                    const float xb = rb * cb, yb = rb * sb_;
                    *(__half2*)(g_xc + (size_t)(bm + row) * 256 + d) = __floats2half2_rn(xa, xb);
                    *(__half2*)(g_yc + (size_t)(bm + row) * 256 + d) = __floats2half2_rn(ya, yb);
                    csx[nt * 2]     += xa;  csx[nt * 2 + 1] += xb;
                    csy[nt * 2]     += ya;  csy[nt * 2 + 1] += yb;
                }
            }
#pragma unroll
        for (int off = 4; off <= 16; off <<= 1)
#pragma unroll
            for (int q = 0; q < 16; q++) {
                csx[q] += __shfl_xor_sync(0xffffffffu, csx[q], off);
                csy[q] += __shfl_xor_sync(0xffffffffu, csy[q], off);
            }
        if (lane < 4) {
#pragma unroll
            for (int nt = 0; nt < 8; nt++) {
#pragma unroll
                for (int e = 0; e < 2; e++) {
                    const int col = nt * 8 + tg * 2 + e;
                    sumx[wm * 64 + col] = csx[nt * 2 + e];
                    sumy[wm * 64 + col] = csy[nt * 2 + e];
                }
            }
        }
    }
    __syncthreads();
    if (t < 128) {        // 64-row chunk sums: warp-row pairs (0,1) and (2,3)
        const int chunk = t >> 6, col = t & 63;
        const float xs = sumx[(chunk * 2) * 64 + col] + sumx[(chunk * 2 + 1) * 64 + col];
        const float ys = sumy[(chunk * 2) * 64 + col] + sumy[(chunk * 2 + 1) * 64 + col];
        const int cg = chunkbase + chunk;
        const int d = j * 64 + col;
        g_xp[cg * BD + b * DD + d] = xs;
        g_yp[cg * BD + b * DD + d] = ys;
    }
}

// ---------------- all 8 KAN layers: 8 lanes cooperate per (b,d) chain ----------------
__global__ __launch_bounds__(256) void k_mlp_all(const float* __restrict__ mw1, const float* __restrict__ mb1,
                                                 const float* __restrict__ mw2, const float* __restrict__ mb2,
                                                 const float* __restrict__ pw1, const float* __restrict__ pb1,
                                                 const float* __restrict__ pw2, const float* __restrict__ pb2) {
    __shared__ float w[NLAYERS * WSTRIDE];
    const int t = threadIdx.x;
    for (int idx = t; idx < NLAYERS * WSTRIDE; idx += 256) {
        const int l = idx / WSTRIDE;
        const int o = idx - l * WSTRIDE;
        float v = 0.0f;
        if      (o < 32)  v = mw1[l * 32 + o];
        else if (o < 64)  v = mb1[l * 32 + (o - 32)];
        else if (o < 96)  v = mw2[l * 32 + (o - 64)];
        else if (o < 160) v = pw1[l * 64 + (o - 96)];
        else if (o < 192) v = pb1[l * 32 + (o - 160)];
        else if (o < 256) v = pw2[l * 64 + (o - 192)];
        else if (o == 256) v = mb2[l];
        else if (o == 257) v = pb2[2 * l];
        else if (o == 258) v = pb2[2 * l + 1];
        w[idx] = v;
    }
    __syncthreads();

    const int s = t & 7;                       // sublane within 8-lane group
    const int k = blockIdx.x * 32 + (t >> 3);  // (b,d) flat, 32 chains/block

    float xs = g_xp[s * BD + k] + g_xp[(s + 8) * BD + k];
    float ys = g_yp[s * BD + k] + g_yp[(s + 8) * BD + k];
#pragma unroll
    for (int off = 1; off < 8; off <<= 1) {
        xs += __shfl_xor_sync(0xffffffffu, xs, off);
        ys += __shfl_xor_sync(0xffffffffu, ys, off);
    }
    float xm = xs * (1.0f / SS), ym = ys * (1.0f / SS);
    float DX = 0.0f, DY = 0.0f;

    for (int l = 0; l < NLAYERS; l++) {
        const float* wl = w + l * WSTRIDE;
        const float ragg  = sqrtf(xm * xm + ym * ym + EPSF);
        const float thagg = atan2f(ym, xm);
        const float logr = logf(ragg + EPSF);
        float s0, c0;
        sincosf(thagg, &s0, &c0);

        float accp = 0.0f, p0p = 0.0f, p1p = 0.0f;
#pragma unroll
        for (int q = 0; q < 4; q++) {
            const int jj = s * 4 + q;
            const float um = fmaf(logr, wl[jj], wl[32 + jj]);
            accp = fmaf(gelu_exact(um), wl[64 + jj], accp);
            const float up = fmaf(s0, wl[96 + jj], fmaf(c0, wl[128 + jj], wl[160 + jj]));
            const float gp = gelu_exact(up);
            p0p = fmaf(gp, wl[192 + 2 * jj],     p0p);
            p1p = fmaf(gp, wl[192 + 2 * jj + 1], p1p);
        }
#pragma unroll
        for (int off = 1; off < 8; off <<= 1) {
            accp += __shfl_xor_sync(0xffffffffu, accp, off);
            p0p  += __shfl_xor_sync(0xffffffffu, p0p,  off);
            p1p  += __shfl_xor_sync(0xffffffffu, p1p,  off);
        }
        const float rt = expf(accp + wl[256]);
        const float p0 = p0p + wl[257], p1 = p1p + wl[258];
        const float nrm = sqrtf(p0 * p0 + p1 * p1 + EPSF);
        const float tht = atan2f(p0 / nrm, p1 / nrm);
        float sd, cd;
        sincosf(tht, &sd, &cd);
        const float dx = rt * cd, dy = rt * sd;
        xm += dx; ym += dy;
        DX += dx; DY += dy;
    }
    if (s == 0) { g_dx[k] = DX; g_dy[k] = DY; }
}

// ---------------- final pass: r = sqrt((xc0+DX)^2 + (yc0+DY)^2 + eps), chunk sums ----------------
// 32 col-groups of 8 (uint4 = 8 halves per load), 8 row-subsets; smem reduce.
__global__ __launch_bounds__(256) void k_final() {
    __shared__ float sh[8][256];   // [rsub][e*32 + c8]
    const int b = blockIdx.y, chunk = blockIdx.x, t = threadIdx.x;
    const int c8 = t & 31, rsub = t >> 5;
    const int dbase = c8 * 8;

    float dxv[8], dyv[8];
    *(float4*)(dxv)     = *(const float4*)(g_dx + b * DD + dbase);
    *(float4*)(dxv + 4) = *(const float4*)(g_dx + b * DD + dbase + 4);
    *(float4*)(dyv)     = *(const float4*)(g_dy + b * DD + dbase);
    *(float4*)(dyv + 4) = *(const float4*)(g_dy + b * DD + dbase + 4);

    float s[8];
#pragma unroll
    for (int e = 0; e < 8; e++) s[e] = 0.0f;

    const size_t rowbase = (size_t)b * SS + (size_t)chunk * 64;
#pragma unroll
    for (int i = 0; i < 8; i++) {
        const size_t idx = (rowbase + rsub + 8 * i) * DD + dbase;
        const uint4 xv = *(const uint4*)(g_xc + idx);
        const uint4 yv = *(const uint4*)(g_yc + idx);
        const __half2* hx = (const __half2*)&xv;
        const __half2* hy = (const __half2*)&yv;
#pragma unroll
        for (int p = 0; p < 4; p++) {
            const float2 xf = __half22float2(hx[p]);
            const float2 yf = __half22float2(hy[p]);
            const float X0 = xf.x + dxv[2 * p],     Y0 = yf.x + dyv[2 * p];
            const float X1 = xf.y + dxv[2 * p + 1], Y1 = yf.y + dyv[2 * p + 1];
            s[2 * p]     += sqrtf(fmaf(X0, X0, fmaf(Y0, Y0, EPSF)));
            s[2 * p + 1] += sqrtf(fmaf(X1, X1, fmaf(Y1, Y1, EPSF)));
        }
    }
#pragma unroll
    for (int e = 0; e < 8; e++) sh[rsub][e * 32 + c8] = s[e];
    __syncthreads();

    // thread t owns output d = t: sum over 8 rsubs at sh[r][(t&7)*32 + (t>>3)]
    const int slot = (t & 7) * 32 + (t >> 3);
    float tot = 0.0f;
#pragma unroll
    for (int r = 0; r < 8; r++) tot += sh[r][slot];
    g_xp[chunk * BD + b * DD + t] = tot;
}

// ---------------- classifier (grid-parallel over class groups) ----------------
__global__ __launch_bounds__(256) void k_cls(const float* __restrict__ w1, const float* __restrict__ b1,
                                             const float* __restrict__ w2, const float* __restrict__ b2,
                                             float* __restrict__ out) {
    __shared__ float p[DD];
    __shared__ float hp[8][33];
    __shared__ float h[KANH];
    const int b = blockIdx.x, cg = blockIdx.y, t = threadIdx.x;
    float s = 0.0f;
#pragma unroll
    for (int c = 0; c < NCHUNK; c++) s += g_xp[c * BD + b * DD + t];
    p[t] = s * (1.0f / SS);
    __syncthreads();
    {
        const int jj = t & 31, sl = t >> 5;
        float a = 0.0f;
#pragma unroll
        for (int q = 0; q < 32; q++) {
            const int d2 = sl * 32 + q;
            a = fmaf(p[d2], w1[d2 * KANH + jj], a);
        }
        hp[sl][jj] = a;
    }
    __syncthreads();
    if (t < KANH) {
        float a = b1[t];
#pragma unroll
        for (int s8 = 0; s8 < 8; s8++) a += hp[s8][t];
        h[t] = gelu_exact(a);
    }
    __syncthreads();
    const int c = cg * 250 + t;
    if (t < 250) {
        float a = b2[c];
#pragma unroll
        for (int jj = 0; jj < KANH; jj++) a = fmaf(h[jj], w2[jj * NCLS + c], a);
        out[b * NCLS + c] = a;
    }
}

// ---------------- launch ----------------
extern "C" void kernel_launch(void* const* d_in, const int* in_sizes, int n_in,
                              void* d_out, int out_size) {
    const float* x   = (const float*)d_in[0];
    const float* ew  = (const float*)d_in[1];
    const float* eb  = (const float*)d_in[2];
    const float* mw1 = (const float*)d_in[3];
    const float* mb1 = (const float*)d_in[4];
    const float* mw2 = (const float*)d_in[5];
    const float* mb2 = (const float*)d_in[6];
    const float* pw1 = (const float*)d_in[7];
    const float* pb1 = (const float*)d_in[8];
    const float* pw2 = (const float*)d_in[9];
    const float* pb2 = (const float*)d_in[10];
    const float* cw1 = (const float*)d_in[11];
    const float* cb1 = (const float*)d_in[12];
    const float* cw2 = (const float*)d_in[13];
    const float* cb2 = (const float*)d_in[14];
    float* out = (float*)d_out;

    cudaFuncSetAttribute(k_gemm, cudaFuncAttributeMaxDynamicSharedMemorySize, GSMEM_TOT);

    k_cvt_w<<<512, 256>>>(ew);

    dim3 ggrid(4, 512);                      // x = d-group j (L2 reuse of A across j), y = mtile
    k_gemm<<<ggrid, 256, GSMEM_TOT>>>(x, eb);

    k_mlp_all<<<BD / 32, 256>>>(mw1, mb1, mw2, mb2, pw1, pb1, pw2, pb2);

    dim3 fgrid(NCHUNK, BB);
    k_final<<<fgrid, 256>>>();

    dim3 cgrid(BB, 4);
    k_cls<<<cgrid, 256>>>(cw1, cb1, cw2, cb2, out);
}